// round 6
// baseline (speedup 1.0000x reference)
#include <cuda_runtime.h>

#define NH 6
#define HD 32
#define NTOK 64
#define HIDDEN 512
#define TBL 225
#define HW 65536
#define ST 68

typedef unsigned long long ull;

// packed fp32x2 ops (Blackwell; ptxas never auto-emits these)
#define FMA2(d, a, b, c) \
    asm("fma.rn.f32x2 %0, %1, %2, %3;" : "=l"(d) : "l"(a), "l"(b), "l"(c))
#define PACK2(d, x) \
    asm("mov.b64 %0, {%1, %1};" : "=l"(d) : "f"(x))
#define UNPACK2(lo, hi, v) \
    asm("mov.b64 {%0, %1}, %2;" : "=f"(lo), "=f"(hi) : "l"(v))

union F4U {
    float4 f4;
    float f[4];
    ull u[2];
};

// device-global scratch (no allocations allowed)
__device__ float g_bt[TBL * NH];
__device__ float g_hscale[NH];
__device__ float g_bias[NH * NTOK * NTOK];

// ---------------------------------------------------------------------------
// Kernel 0a: CPB MLP, one block per table row (225 blocks) + head scales.
// ---------------------------------------------------------------------------
__global__ void __launch_bounds__(128) bias_mlp_kernel(
    const float* __restrict__ table,
    const float* __restrict__ logit_scale,
    const float* __restrict__ w1,
    const float* __restrict__ b1,
    const float* __restrict__ w2) {
    const int row = blockIdx.x;
    const int tid = threadIdx.x;

    if (row == 0 && tid < NH) {
        const float LOGIT_MAX = 4.605170185988091368f; // log(100)
        g_hscale[tid] = expf(fminf(logit_scale[tid], LOGIT_MAX)) * rsqrtf((float)HD);
    }

    const float t0 = table[row * 2 + 0];
    const float t1 = table[row * 2 + 1];
    float acc[NH];
#pragma unroll
    for (int h = 0; h < NH; h++) acc[h] = 0.f;

    for (int j = tid; j < HIDDEN; j += 128) {
        float hv = fmaf(t0, w1[j], fmaf(t1, w1[HIDDEN + j], b1[j]));
        hv = fmaxf(hv, 0.f);
#pragma unroll
        for (int h = 0; h < NH; h++) acc[h] = fmaf(hv, w2[j * NH + h], acc[h]);
    }

#pragma unroll
    for (int h = 0; h < NH; h++) {
#pragma unroll
        for (int o = 16; o > 0; o >>= 1)
            acc[h] += __shfl_xor_sync(0xffffffffu, acc[h], o);
    }
    __shared__ float red[4][NH];
    const int warp = tid >> 5;
    if ((tid & 31) == 0) {
#pragma unroll
        for (int h = 0; h < NH; h++) red[warp][h] = acc[h];
    }
    __syncthreads();
    if (tid == 0) {
#pragma unroll
        for (int h = 0; h < NH; h++)
            g_bt[row * NH + h] = red[0][h] + red[1][h] + red[2][h] + red[3][h];
    }
}

// ---------------------------------------------------------------------------
// Kernel 0b: expand bias -> g_bias[h][n][m] = 16*sigmoid(bt[index[n][m]][h])
// ---------------------------------------------------------------------------
__global__ void bias_gather_kernel(const int* __restrict__ index) {
    int gid = blockIdx.x * blockDim.x + threadIdx.x;
    if (gid >= NH * NTOK * NTOK) return;
    int h = gid >> 12;
    int nm = gid & 4095;
    int r = index[nm];
    float bv = g_bt[r * NH + h];
    g_bias[gid] = 16.f / (1.f + __expf(-bv));
}

// ---------------------------------------------------------------------------
// Main kernel: one CTA per (window, head). 64 threads, 8 CTAs/SM.
//  8x8 tiles in phase 1; phase 3 split in two 4-row halves (no reg spills).
// ---------------------------------------------------------------------------
__global__ void __launch_bounds__(64, 8) win_attn_kernel(
    const float* __restrict__ qkv,
    const float* __restrict__ mask,
    const float* __restrict__ bias,
    float* __restrict__ out)
{
    __shared__ __align__(16) float pool[3 * HD * ST];
    float* const sq = pool;                 // [32][68]
    float* const sk = pool + HD * ST;       // [32][68]
    float* const sv = pool + 2 * HD * ST;   // [32][68]
    float* const ss = pool;                 // [64][68] aliases sq+sk (exact fit)

    const int tid = threadIdx.x;
    const int bid = blockIdx.x;
    const int h = bid % NH;
    const int b_ = bid / NH;           // 0..2047
    const int b = b_ >> 10;            // batch
    const int w = b_ & 1023;           // window id within image
    const int wy = w >> 5, wx = w & 31;
    // roll(-4,-4): window pixel (i,j) <- original ((wy*8+i+4)&255, (wx*8+j+4)&255)
    const int y0 = wy * 8 + 4;
    const int x0 = wx * 8 + 4;

    // channel = t*384 + b*192 + h*32 + d   (qkv is (3,B,192,H,W))
    const int chbase = b * 192 + h * 32;

    // ---- load q,k,v: 1536 float4 loads (24/thread), into smem [d][n] ----
#pragma unroll
    for (int k4 = 0; k4 < 24; k4++) {
        int idx4 = tid + k4 * 64;
        int t = idx4 >> 9;              // 0..2
        int d = (idx4 >> 4) & 31;
        int q16 = idx4 & 15;            // 16 float4 per (t,d) plane
        int i = q16 >> 1;               // window row 0..7
        int j0 = (q16 & 1) << 2;        // 0 or 4
        int y = (y0 + i) & 255;
        int x = (x0 + j0) & 255;        // 4-aligned, never splits across wrap
        const float4 val = *(const float4*)(qkv + (chbase + t * 384 + d) * HW + y * 256 + x);
        float* dst = (t == 0 ? sq : (t == 1 ? sk : sv)) + d * ST + i * 8 + j0;
        *(float4*)dst = val;
    }
    __syncthreads();

    const float scale = g_hscale[h];
    const float* mask_w = mask + w * 4096;
    const float* bias_h = bias + h * 4096;

    const int mi = tid & 7;
    const int m0 = mi * 4;              // m set = {m0..m0+3} U {m0+32..m0+35}
    const int ng = tid >> 3;
    const int n0 = ng * 8;              // 8 consecutive n rows (one window row)

    // ---- phase 1: S = q.k over 8n x 8m tile ----
    ull acc2[8][4];
#pragma unroll
    for (int a = 0; a < 8; a++)
#pragma unroll
        for (int c = 0; c < 4; c++) acc2[a][c] = 0ull;

    {
        const float* pq = sq + n0;
        const float* pk = sk + m0;
#pragma unroll 2
        for (int d = 0; d < 32; d++) {
            F4U qa0, qa1, kb0, kb1;
            qa0.f4 = *(const float4*)(pq + d * ST);        // broadcast (8 lanes same)
            qa1.f4 = *(const float4*)(pq + d * ST + 4);
            kb0.f4 = *(const float4*)(pk + d * ST);        // conflict-free
            kb1.f4 = *(const float4*)(pk + d * ST + 32);
#pragma unroll
            for (int a = 0; a < 4; a++) {
                ull qp;
                PACK2(qp, qa0.f[a]);
                FMA2(acc2[a][0], qp, kb0.u[0], acc2[a][0]);
                FMA2(acc2[a][1], qp, kb0.u[1], acc2[a][1]);
                FMA2(acc2[a][2], qp, kb1.u[0], acc2[a][2]);
                FMA2(acc2[a][3], qp, kb1.u[1], acc2[a][3]);
            }
#pragma unroll
            for (int a = 0; a < 4; a++) {
                ull qp;
                PACK2(qp, qa1.f[a]);
                FMA2(acc2[4 + a][0], qp, kb0.u[0], acc2[4 + a][0]);
                FMA2(acc2[4 + a][1], qp, kb0.u[1], acc2[4 + a][1]);
                FMA2(acc2[4 + a][2], qp, kb1.u[0], acc2[4 + a][2]);
                FMA2(acc2[4 + a][3], qp, kb1.u[1], acc2[4 + a][3]);
            }
        }
    }
    __syncthreads();   // all reads of sq/sk complete before P overwrites them

    // ---- epilogue: bias + mask + register softmax, write P into ss ----
    {
#pragma unroll
        for (int a = 0; a < 8; a++) {
            const int n = n0 + a;
            F4U cm0, cm1, cb0, cb1;
            cm0.f4 = *(const float4*)(mask_w + n * 64 + m0);
            cm1.f4 = *(const float4*)(mask_w + n * 64 + m0 + 32);
            cb0.f4 = *(const float4*)(bias_h + n * 64 + m0);
            cb1.f4 = *(const float4*)(bias_h + n * 64 + m0 + 32);
            float s[8];
#pragma unroll
            for (int c = 0; c < 2; c++) {
                float lo, hi;
                UNPACK2(lo, hi, acc2[a][c]);
                s[2 * c]     = fmaf(lo, scale, cb0.f[2 * c] + cm0.f[2 * c]);
                s[2 * c + 1] = fmaf(hi, scale, cb0.f[2 * c + 1] + cm0.f[2 * c + 1]);
            }
#pragma unroll
            for (int c = 0; c < 2; c++) {
                float lo, hi;
                UNPACK2(lo, hi, acc2[a][2 + c]);
                s[4 + 2 * c]     = fmaf(lo, scale, cb1.f[2 * c] + cm1.f[2 * c]);
                s[4 + 2 * c + 1] = fmaf(hi, scale, cb1.f[2 * c + 1] + cm1.f[2 * c + 1]);
            }
            float mx = -1e30f;
#pragma unroll
            for (int c = 0; c < 8; c++) mx = fmaxf(mx, s[c]);
            mx = fmaxf(mx, __shfl_xor_sync(0xffffffffu, mx, 1));
            mx = fmaxf(mx, __shfl_xor_sync(0xffffffffu, mx, 2));
            mx = fmaxf(mx, __shfl_xor_sync(0xffffffffu, mx, 4));
            float sum = 0.f;
#pragma unroll
            for (int c = 0; c < 8; c++) {
                s[c] = __expf(s[c] - mx);
                sum += s[c];
            }
            sum += __shfl_xor_sync(0xffffffffu, sum, 1);
            sum += __shfl_xor_sync(0xffffffffu, sum, 2);
            sum += __shfl_xor_sync(0xffffffffu, sum, 4);
            const float rinv = 1.f / sum;
            float4 p0 = make_float4(s[0] * rinv, s[1] * rinv, s[2] * rinv, s[3] * rinv);
            float4 p1 = make_float4(s[4] * rinv, s[5] * rinv, s[6] * rinv, s[7] * rinv);
            *(float4*)&ss[n * ST + m0] = p0;
            *(float4*)&ss[n * ST + m0 + 32] = p1;
        }
    }
    __syncthreads();

    // ---- phase 3: O[d][n] = V[d][:] . P[n][:]^T, two 4-row halves ----
    // d in {d0, d0+8, d0+16, d0+24}, d0 = mi -> conflict-free V loads.
    {
        const int d0 = mi;
        const float* pv = sv + d0 * ST;
        const int y = (y0 + ng) & 255;

#pragma unroll
        for (int half = 0; half < 2; half++) {
            const int n0h = n0 + half * 4;
            ull o2[4][4];
#pragma unroll
            for (int j = 0; j < 4; j++)
#pragma unroll
                for (int i = 0; i < 4; i++) o2[j][i] = 0ull;

            const float* pp = ss + n0h * ST;
#pragma unroll 2
            for (int mb = 0; mb < 16; mb++) {
                const int m = mb * 4;
                F4U v[4], p[4];
#pragma unroll
                for (int i = 0; i < 4; i++) v[i].f4 = *(const float4*)(pv + i * 8 * ST + m);
#pragma unroll
                for (int j = 0; j < 4; j++) p[j].f4 = *(const float4*)(pp + j * ST + m);
#pragma unroll
                for (int j = 0; j < 4; j++)
#pragma unroll
                    for (int i = 0; i < 4; i++) {
                        FMA2(o2[j][i], v[i].u[0], p[j].u[0], o2[j][i]);
                        FMA2(o2[j][i], v[i].u[1], p[j].u[1], o2[j][i]);
                    }
            }

            // store: rows n0h..n0h+3 = cols (4*half)..(4*half+3) of window row ng
            const int xh = (x0 + 4 * half) & 255;   // 4-aligned, contiguous
#pragma unroll
            for (int i = 0; i < 4; i++) {
                const int d = d0 + i * 8;
                float ov[4];
#pragma unroll
                for (int j = 0; j < 4; j++) {
                    float lo, hi;
                    UNPACK2(lo, hi, o2[j][i]);
                    ov[j] = lo + hi;
                }
                *(float4*)(out + (chbase + d) * HW + y * 256 + xh) =
                    make_float4(ov[0], ov[1], ov[2], ov[3]);
            }
        }
    }
}

// ---------------------------------------------------------------------------
extern "C" void kernel_launch(void* const* d_in, const int* in_sizes, int n_in,
                              void* d_out, int out_size) {
    const float* qkv         = (const float*)d_in[0];
    const float* table       = (const float*)d_in[1];
    const int*   index       = (const int*)  d_in[2];
    const float* mask        = (const float*)d_in[3];
    const float* logit_scale = (const float*)d_in[4];
    const float* w1          = (const float*)d_in[5];
    const float* b1          = (const float*)d_in[6];
    const float* w2          = (const float*)d_in[7];
    float* out = (float*)d_out;

    cudaFuncSetAttribute(win_attn_kernel,
                         cudaFuncAttributePreferredSharedMemoryCarveout, 100);

    bias_mlp_kernel<<<TBL, 128>>>(table, logit_scale, w1, b1, w2);
    bias_gather_kernel<<<96, 256>>>(index);

    float* d_bias = nullptr;
    cudaGetSymbolAddress((void**)&d_bias, g_bias);
    win_attn_kernel<<<2 * 1024 * NH, 64>>>(qkv, mask, d_bias, out);
    (void)in_sizes; (void)n_in; (void)out_size;
}

// round 7
// speedup vs baseline: 1.0654x; 1.0654x over previous
#include <cuda_runtime.h>

#define NH 6
#define HD 32
#define NTOK 64
#define HIDDEN 512
#define TBL 225
#define HW 65536
#define ST 68

typedef unsigned long long ull;

// packed fp32x2 ops (Blackwell; ptxas never auto-emits these)
#define FMA2(d, a, b, c) \
    asm("fma.rn.f32x2 %0, %1, %2, %3;" : "=l"(d) : "l"(a), "l"(b), "l"(c))
#define PACK2(d, x) \
    asm("mov.b64 %0, {%1, %1};" : "=l"(d) : "f"(x))
#define UNPACK2(lo, hi, v) \
    asm("mov.b64 {%0, %1}, %2;" : "=f"(lo), "=f"(hi) : "l"(v))

union F4U {
    float4 f4;
    float f[4];
    ull u[2];
};

// device-global scratch (no allocations allowed)
__device__ float g_bt[TBL * NH];
__device__ float g_hscale[NH];
__device__ float g_bias[NH * NTOK * NTOK];

// ---------------------------------------------------------------------------
// Kernel 0a: CPB MLP, one block per table row (225 blocks) + head scales.
// ---------------------------------------------------------------------------
__global__ void __launch_bounds__(128) bias_mlp_kernel(
    const float* __restrict__ table,
    const float* __restrict__ logit_scale,
    const float* __restrict__ w1,
    const float* __restrict__ b1,
    const float* __restrict__ w2) {
    const int row = blockIdx.x;
    const int tid = threadIdx.x;

    if (row == 0 && tid < NH) {
        const float LOGIT_MAX = 4.605170185988091368f; // log(100)
        g_hscale[tid] = expf(fminf(logit_scale[tid], LOGIT_MAX)) * rsqrtf((float)HD);
    }

    const float t0 = table[row * 2 + 0];
    const float t1 = table[row * 2 + 1];
    float acc[NH];
#pragma unroll
    for (int h = 0; h < NH; h++) acc[h] = 0.f;

    for (int j = tid; j < HIDDEN; j += 128) {
        float hv = fmaf(t0, w1[j], fmaf(t1, w1[HIDDEN + j], b1[j]));
        hv = fmaxf(hv, 0.f);
#pragma unroll
        for (int h = 0; h < NH; h++) acc[h] = fmaf(hv, w2[j * NH + h], acc[h]);
    }

#pragma unroll
    for (int h = 0; h < NH; h++) {
#pragma unroll
        for (int o = 16; o > 0; o >>= 1)
            acc[h] += __shfl_xor_sync(0xffffffffu, acc[h], o);
    }
    __shared__ float red[4][NH];
    const int warp = tid >> 5;
    if ((tid & 31) == 0) {
#pragma unroll
        for (int h = 0; h < NH; h++) red[warp][h] = acc[h];
    }
    __syncthreads();
    if (tid == 0) {
#pragma unroll
        for (int h = 0; h < NH; h++)
            g_bt[row * NH + h] = red[0][h] + red[1][h] + red[2][h] + red[3][h];
    }
}

// ---------------------------------------------------------------------------
// Kernel 0b: expand bias -> g_bias[h][n][m] = 16*sigmoid(bt[index[n][m]][h])
// ---------------------------------------------------------------------------
__global__ void bias_gather_kernel(const int* __restrict__ index) {
    int gid = blockIdx.x * blockDim.x + threadIdx.x;
    if (gid >= NH * NTOK * NTOK) return;
    int h = gid >> 12;
    int nm = gid & 4095;
    int r = index[nm];
    float bv = g_bt[r * NH + h];
    g_bias[gid] = 16.f / (1.f + __expf(-bv));
}

// ---------------------------------------------------------------------------
// Main kernel: one CTA per (window, head). 128 threads, 5 CTAs/SM.
//  R4 structure + (bias+mask) staged into smem at CTA start (latency hiding).
// ---------------------------------------------------------------------------
__global__ void __launch_bounds__(128, 5) win_attn_kernel(
    const float* __restrict__ qkv,
    const float* __restrict__ mask,
    const float* __restrict__ bias,
    float* __restrict__ out)
{
    __shared__ __align__(16) float sq[HD * ST];
    __shared__ __align__(16) float sk[HD * ST];
    __shared__ __align__(16) float sv[HD * ST];
    __shared__ __align__(16) float ss[NTOK * ST];   // combined bias+mask, then P

    const int tid = threadIdx.x;
    const int bid = blockIdx.x;
    const int h = bid % NH;
    const int b_ = bid / NH;           // 0..2047
    const int b = b_ >> 10;            // batch
    const int w = b_ & 1023;           // window id within image
    const int wy = w >> 5, wx = w & 31;
    // roll(-4,-4): window pixel (i,j) <- original ((wy*8+i+4)&255, (wx*8+j+4)&255)
    const int y0 = wy * 8 + 4;
    const int x0 = wx * 8 + 4;

    // channel = t*384 + b*192 + h*32 + d   (qkv is (3,B,192,H,W))
    const int chbase = b * 192 + h * 32;

    const float* mask_w = mask + w * 4096;
    const float* bias_h = bias + h * 4096;

    // ---- load q,k,v: 1536 float4 loads (12/thread), into smem [d][n] ----
#pragma unroll
    for (int k4 = 0; k4 < 12; k4++) {
        int idx4 = tid + k4 * 128;
        int t = idx4 >> 9;              // 0..2 (constant per unrolled iter)
        int d = (idx4 >> 4) & 31;
        int q16 = idx4 & 15;            // 16 float4 per (t,d) plane
        int i = q16 >> 1;               // window row 0..7
        int j0 = (q16 & 1) << 2;        // 0 or 4
        int y = (y0 + i) & 255;
        int x = (x0 + j0) & 255;        // 4-aligned, never splits across wrap
        const float4 val = *(const float4*)(qkv + (chbase + t * 384 + d) * HW + y * 256 + x);
        float* dst = (t == 0 ? sq : (t == 1 ? sk : sv)) + d * ST + i * 8 + j0;
        *(float4*)dst = val;
    }

    // ---- stage combined = bias + mask into ss (overlaps qkv loads) ----
#pragma unroll
    for (int i = 0; i < 8; i++) {
        int idx4 = tid + i * 128;       // 0..1023 float4
        int n = idx4 >> 4;              // 0..63
        int mq = (idx4 & 15) << 2;      // 0,4,...,60
        float4 bv = *(const float4*)(bias_h + n * 64 + mq);
        float4 mv = *(const float4*)(mask_w + n * 64 + mq);
        *(float4*)&ss[n * ST + mq] =
            make_float4(bv.x + mv.x, bv.y + mv.y, bv.z + mv.z, bv.w + mv.w);
    }
    __syncthreads();

    const float scale = g_hscale[h];

    // ---- phase 1: S = scale*q.k + combined ----
    // thread tile: 4 n-rows x 8 m-cols, m set = {m0..m0+3} U {m0+32..m0+35},
    // m0 = (tid&7)*4 -> all K loads hit 8 distinct bank groups (conflict-free).
    {
        const int m0 = (tid & 7) * 4;
        const int n0 = (tid >> 3) * 4;
        ull acc2[4][4];
#pragma unroll
        for (int a = 0; a < 4; a++)
#pragma unroll
            for (int c = 0; c < 4; c++) acc2[a][c] = 0ull;

        const float* pq = sq + n0;
        const float* pk = sk + m0;
#pragma unroll 4
        for (int d = 0; d < 32; d++) {
            F4U qa, kb0, kb1;
            qa.f4  = *(const float4*)(pq + d * ST);
            kb0.f4 = *(const float4*)(pk + d * ST);
            kb1.f4 = *(const float4*)(pk + d * ST + 32);
#pragma unroll
            for (int a = 0; a < 4; a++) {
                ull qp;
                PACK2(qp, qa.f[a]);
                FMA2(acc2[a][0], qp, kb0.u[0], acc2[a][0]);
                FMA2(acc2[a][1], qp, kb0.u[1], acc2[a][1]);
                FMA2(acc2[a][2], qp, kb1.u[0], acc2[a][2]);
                FMA2(acc2[a][3], qp, kb1.u[1], acc2[a][3]);
            }
        }

        // epilogue: combined (from smem) + register softmax (row = 8 lanes)
#pragma unroll
        for (int a = 0; a < 4; a++) {
            const int n = n0 + a;
            F4U c0, c1;
            c0.f4 = *(const float4*)&ss[n * ST + m0];
            c1.f4 = *(const float4*)&ss[n * ST + m0 + 32];
            float s[8];
#pragma unroll
            for (int c = 0; c < 2; c++) {
                float lo, hi;
                UNPACK2(lo, hi, acc2[a][c]);
                s[2 * c]     = fmaf(lo, scale, c0.f[2 * c]);
                s[2 * c + 1] = fmaf(hi, scale, c0.f[2 * c + 1]);
            }
#pragma unroll
            for (int c = 0; c < 2; c++) {
                float lo, hi;
                UNPACK2(lo, hi, acc2[a][2 + c]);
                s[4 + 2 * c]     = fmaf(lo, scale, c1.f[2 * c]);
                s[4 + 2 * c + 1] = fmaf(hi, scale, c1.f[2 * c + 1]);
            }
            float mx = -1e30f;
#pragma unroll
            for (int c = 0; c < 8; c++) mx = fmaxf(mx, s[c]);
            mx = fmaxf(mx, __shfl_xor_sync(0xffffffffu, mx, 1));
            mx = fmaxf(mx, __shfl_xor_sync(0xffffffffu, mx, 2));
            mx = fmaxf(mx, __shfl_xor_sync(0xffffffffu, mx, 4));
            float sum = 0.f;
#pragma unroll
            for (int c = 0; c < 8; c++) {
                s[c] = __expf(s[c] - mx);
                sum += s[c];
            }
            sum += __shfl_xor_sync(0xffffffffu, sum, 1);
            sum += __shfl_xor_sync(0xffffffffu, sum, 2);
            sum += __shfl_xor_sync(0xffffffffu, sum, 4);
            const float rinv = 1.f / sum;
            float4 p0 = make_float4(s[0] * rinv, s[1] * rinv, s[2] * rinv, s[3] * rinv);
            float4 p1 = make_float4(s[4] * rinv, s[5] * rinv, s[6] * rinv, s[7] * rinv);
            // overwrite exactly this thread's combined values with P
            *(float4*)&ss[n * ST + m0] = p0;
            *(float4*)&ss[n * ST + m0 + 32] = p1;
        }
    }
    __syncthreads();

    // ---- phase 3: O[d][n] = V[d][:] . P[n][:]^T ----
    // thread tile: d in {d0, d0+8, d0+16, d0+24} (d0 = tid&7) x 4 n-cols
    // -> V loads hit 8 distinct bank groups (conflict-free).
    {
        const int d0 = tid & 7;
        const int n0 = (tid >> 3) * 4;
        ull o2[4][4];
#pragma unroll
        for (int i = 0; i < 4; i++)
#pragma unroll
            for (int j = 0; j < 4; j++) o2[i][j] = 0ull;

        const float* pv = sv + d0 * ST;
        const float* pp = ss + n0 * ST;
#pragma unroll 4
        for (int mb = 0; mb < 16; mb++) {
            const int m = mb * 4;
            F4U p[4], v[4];
#pragma unroll
            for (int j = 0; j < 4; j++) p[j].f4 = *(const float4*)(pp + j * ST + m);
#pragma unroll
            for (int i = 0; i < 4; i++) v[i].f4 = *(const float4*)(pv + i * 8 * ST + m);
#pragma unroll
            for (int i = 0; i < 4; i++)
#pragma unroll
                for (int j = 0; j < 4; j++) {
                    FMA2(o2[i][j], v[i].u[0], p[j].u[0], o2[i][j]);
                    FMA2(o2[i][j], v[i].u[1], p[j].u[1], o2[i][j]);
                }
        }

        // store: n0..n0+3 lie in one window row (n0 % 8 in {0,4}); roll cancels.
        const int i2 = n0 >> 3;
        const int j0s = n0 & 7;
        const int y = (y0 + i2) & 255;
        const int xs = (x0 + j0s) & 255;   // 4-aligned, contiguous
#pragma unroll
        for (int i = 0; i < 4; i++) {
            float ov[4];
#pragma unroll
            for (int j = 0; j < 4; j++) {
                float lo, hi;
                UNPACK2(lo, hi, o2[i][j]);
                ov[j] = lo + hi;
            }
            *(float4*)(out + (chbase + d0 + i * 8) * HW + y * 256 + xs) =
                make_float4(ov[0], ov[1], ov[2], ov[3]);
        }
    }
}

// ---------------------------------------------------------------------------
extern "C" void kernel_launch(void* const* d_in, const int* in_sizes, int n_in,
                              void* d_out, int out_size) {
    const float* qkv         = (const float*)d_in[0];
    const float* table       = (const float*)d_in[1];
    const int*   index       = (const int*)  d_in[2];
    const float* mask        = (const float*)d_in[3];
    const float* logit_scale = (const float*)d_in[4];
    const float* w1          = (const float*)d_in[5];
    const float* b1          = (const float*)d_in[6];
    const float* w2          = (const float*)d_in[7];
    float* out = (float*)d_out;

    cudaFuncSetAttribute(win_attn_kernel,
                         cudaFuncAttributePreferredSharedMemoryCarveout, 100);

    bias_mlp_kernel<<<TBL, 128>>>(table, logit_scale, w1, b1, w2);
    bias_gather_kernel<<<96, 256>>>(index);

    float* d_bias = nullptr;
    cudaGetSymbolAddress((void**)&d_bias, g_bias);
    win_attn_kernel<<<2 * 1024 * NH, 128>>>(qkv, mask, d_bias, out);
    (void)in_sizes; (void)n_in; (void)out_size;
}

// round 8
// speedup vs baseline: 1.1761x; 1.1039x over previous
#include <cuda_runtime.h>
#include <cuda_bf16.h>

#define NH 6
#define HD 32
#define NTOK 64
#define HIDDEN 512
#define TBL 225
#define HW 65536

// Q/K smem: [64 rows][36 words]; row = token, words 0..15 = k-pairs hi,
// words 16..31 = k-pairs lo, 4 pad. banks(row*36+c) = 4*row+c -> conflict-free frags.
#define STQK 36
// V smem: [32 rows][68 words]; row = d, words 0..31 = m-pairs hi, 32..63 lo, 4 pad.
#define STV 68
// combined bias+mask fp32: [64][68]
#define STC 68

// m16n8k16 row.col f32.bf16.bf16.f32
#define MMA(D, A, b0, b1) \
    asm("mma.sync.aligned.m16n8k16.row.col.f32.bf16.bf16.f32 " \
        "{%0,%1,%2,%3},{%4,%5,%6,%7},{%8,%9},{%0,%1,%2,%3};" \
        : "+f"(D[0]), "+f"(D[1]), "+f"(D[2]), "+f"(D[3]) \
        : "r"(A[0]), "r"(A[1]), "r"(A[2]), "r"(A[3]), "r"(b0), "r"(b1))

__device__ __forceinline__ unsigned pack2(float lo, float hi) {
    unsigned r;
    asm("cvt.rn.bf16x2.f32 %0, %1, %2;" : "=r"(r) : "f"(hi), "f"(lo));
    return r;  // low half = lo, high half = hi
}
__device__ __forceinline__ float bflo(unsigned w) { return __uint_as_float(w << 16); }
__device__ __forceinline__ float bfhi(unsigned w) { return __uint_as_float(w & 0xffff0000u); }

// device-global scratch (no allocations allowed)
__device__ float g_bt[TBL * NH];
__device__ float g_hscale[NH];
__device__ float g_bias[NH * NTOK * NTOK];

// ---------------------------------------------------------------------------
// Kernel 0a: CPB MLP, one block per table row (225 blocks) + head scales.
// ---------------------------------------------------------------------------
__global__ void __launch_bounds__(128) bias_mlp_kernel(
    const float* __restrict__ table,
    const float* __restrict__ logit_scale,
    const float* __restrict__ w1,
    const float* __restrict__ b1,
    const float* __restrict__ w2) {
    const int row = blockIdx.x;
    const int tid = threadIdx.x;

    if (row == 0 && tid < NH) {
        const float LOGIT_MAX = 4.605170185988091368f; // log(100)
        g_hscale[tid] = expf(fminf(logit_scale[tid], LOGIT_MAX)) * rsqrtf((float)HD);
    }

    const float t0 = table[row * 2 + 0];
    const float t1 = table[row * 2 + 1];
    float acc[NH];
#pragma unroll
    for (int h = 0; h < NH; h++) acc[h] = 0.f;

    for (int j = tid; j < HIDDEN; j += 128) {
        float hv = fmaf(t0, w1[j], fmaf(t1, w1[HIDDEN + j], b1[j]));
        hv = fmaxf(hv, 0.f);
#pragma unroll
        for (int h = 0; h < NH; h++) acc[h] = fmaf(hv, w2[j * NH + h], acc[h]);
    }

#pragma unroll
    for (int h = 0; h < NH; h++) {
#pragma unroll
        for (int o = 16; o > 0; o >>= 1)
            acc[h] += __shfl_xor_sync(0xffffffffu, acc[h], o);
    }
    __shared__ float red[4][NH];
    const int warp = tid >> 5;
    if ((tid & 31) == 0) {
#pragma unroll
        for (int h = 0; h < NH; h++) red[warp][h] = acc[h];
    }
    __syncthreads();
    if (tid == 0) {
#pragma unroll
        for (int h = 0; h < NH; h++)
            g_bt[row * NH + h] = red[0][h] + red[1][h] + red[2][h] + red[3][h];
    }
}

// ---------------------------------------------------------------------------
// Kernel 0b: expand bias -> g_bias[h][n][m] = 16*sigmoid(bt[index[n][m]][h])
// ---------------------------------------------------------------------------
__global__ void bias_gather_kernel(const int* __restrict__ index) {
    int gid = blockIdx.x * blockDim.x + threadIdx.x;
    if (gid >= NH * NTOK * NTOK) return;
    int h = gid >> 12;
    int nm = gid & 4095;
    int r = index[nm];
    float bv = g_bt[r * NH + h];
    g_bias[gid] = 16.f / (1.f + __expf(-bv));
}

// ---------------------------------------------------------------------------
// Main kernel: one CTA per (window, head). 128 threads (4 warps), 5 CTAs/SM.
//  Tensor-core path: bf16x3 split mma.sync for QK^T and PV.
//  Softmax entirely in fragments; P never leaves registers; one barrier total.
// ---------------------------------------------------------------------------
__global__ void __launch_bounds__(128, 5) win_attn_kernel(
    const float* __restrict__ qkv,
    const float* __restrict__ mask,
    const float* __restrict__ bias,
    float* __restrict__ out)
{
    __shared__ __align__(16) unsigned sqw[NTOK * STQK];   // Q bf16 hi/lo
    __shared__ __align__(16) unsigned skw[NTOK * STQK];   // K bf16 hi/lo
    __shared__ __align__(16) unsigned svw[HD * STV];      // V bf16 hi/lo, [d][m]
    __shared__ __align__(16) float scomb[NTOK * STC];     // bias + mask fp32

    const int tid = threadIdx.x;
    const int bid = blockIdx.x;
    const int h = bid % NH;
    const int b_ = bid / NH;           // 0..2047
    const int b = b_ >> 10;            // batch
    const int w = b_ & 1023;           // window id within image
    const int wy = w >> 5, wx = w & 31;
    // roll(-4,-4): window pixel (i,j) <- original ((wy*8+i+4)&255, (wx*8+j+4)&255)
    const int y0 = wy * 8 + 4;
    const int x0 = wx * 8 + 4;

    // channel = t*384 + b*192 + h*32 + d   (qkv is (3,B,192,H,W))
    const int chbase = b * 192 + h * 32;

    const float* mask_w = mask + w * 4096;
    const float* bias_h = bias + h * 4096;

    // ---- stage Q,K -> [n][k] bf16 hi/lo ----
#pragma unroll
    for (int l = 0; l < 8; l++) {
        int idx4 = tid + l * 128;       // 0..1023
        int t = idx4 >> 9;              // 0 = q, 1 = k
        int k = (idx4 >> 4) & 31;
        int q16 = idx4 & 15;
        int i = q16 >> 1;
        int j0 = (q16 & 1) << 2;
        int y = (y0 + i) & 255;
        int x = (x0 + j0) & 255;        // 4-aligned, never splits across wrap
        float4 val = *(const float4*)(qkv + (chbase + t * 384 + k) * HW + y * 256 + x);
        unsigned* basep = (t == 0) ? sqw : skw;
        int n = i * 8 + j0;
        float vf[4] = {val.x, val.y, val.z, val.w};
#pragma unroll
        for (int e = 0; e < 4; e++) {
            float xv = vf[e];
            __nv_bfloat16 hb = __float2bfloat16(xv);
            float hf = __bfloat162float(hb);
            __nv_bfloat16 lb = __float2bfloat16(xv - hf);
            __nv_bfloat16* rowp = (__nv_bfloat16*)(basep + (n + e) * STQK);
            rowp[k] = hb;           // hi halfwords 0..31
            rowp[32 + k] = lb;      // lo halfwords 32..63
        }
    }
    // ---- stage V -> [d][m] bf16 hi/lo ----
#pragma unroll
    for (int l = 0; l < 4; l++) {
        int idx4 = tid + l * 128;       // 0..511
        int d = idx4 >> 4;              // 0..31
        int q16 = idx4 & 15;
        int i = q16 >> 1;
        int j0 = (q16 & 1) << 2;
        int y = (y0 + i) & 255;
        int x = (x0 + j0) & 255;
        float4 val = *(const float4*)(qkv + (chbase + 768 + d) * HW + y * 256 + x);
        int n = i * 8 + j0;
        float vf[4] = {val.x, val.y, val.z, val.w};
        __nv_bfloat16* rowp = (__nv_bfloat16*)(svw + d * STV);
#pragma unroll
        for (int e = 0; e < 4; e++) {
            float xv = vf[e];
            __nv_bfloat16 hb = __float2bfloat16(xv);
            float hf = __bfloat162float(hb);
            __nv_bfloat16 lb = __float2bfloat16(xv - hf);
            rowp[n + e] = hb;       // m hi halfwords 0..63
            rowp[64 + n + e] = lb;  // m lo halfwords 64..127
        }
    }
    // ---- stage combined = bias + mask ----
#pragma unroll
    for (int l = 0; l < 8; l++) {
        int idx4 = tid + l * 128;       // 0..1023 float4
        int n = idx4 >> 4;
        int mq = (idx4 & 15) << 2;
        float4 bv = *(const float4*)(bias_h + n * 64 + mq);
        float4 mv = *(const float4*)(mask_w + n * 64 + mq);
        *(float4*)&scomb[n * STC + mq] =
            make_float4(bv.x + mv.x, bv.y + mv.y, bv.z + mv.z, bv.w + mv.w);
    }
    __syncthreads();

    const int lane = tid & 31;
    const int wrp = tid >> 5;           // warp owns S rows 16*wrp..16*wrp+15
    const int r = lane >> 2;            // groupID
    const int cq = lane & 3;            // threadID in group
    const int rowA = wrp * 16 + r;      // global token row (half A); half B = +8

    // ---- QK^T: A fragments (Q) hoisted; loop 8 n-tiles x 2 k-steps x 3 splits ----
    unsigned ah[2][4], al[2][4];
#pragma unroll
    for (int ks = 0; ks < 2; ks++) {
        const unsigned* q0 = sqw + rowA * STQK + 8 * ks + cq;
        const unsigned* q1 = sqw + (rowA + 8) * STQK + 8 * ks + cq;
        ah[ks][0] = q0[0];  ah[ks][1] = q1[0];  ah[ks][2] = q0[4];  ah[ks][3] = q1[4];
        al[ks][0] = q0[16]; al[ks][1] = q1[16]; al[ks][2] = q0[20]; al[ks][3] = q1[20];
    }

    float D[8][4];
#pragma unroll
    for (int t = 0; t < 8; t++)
#pragma unroll
        for (int c = 0; c < 4; c++) D[t][c] = 0.f;

#pragma unroll
    for (int nt = 0; nt < 8; nt++) {
#pragma unroll
        for (int ks = 0; ks < 2; ks++) {
            const unsigned* kp = skw + (nt * 8 + r) * STQK + 8 * ks + cq;
            unsigned bh0 = kp[0], bh1 = kp[4];
            unsigned bl0 = kp[16], bl1 = kp[20];
            MMA(D[nt], ah[ks], bh0, bh1);
            MMA(D[nt], ah[ks], bl0, bl1);
            MMA(D[nt], al[ks], bh0, bh1);
        }
    }

    // ---- softmax in fragments (rows rowA and rowA+8, 4 lanes per row) ----
    const float scale = g_hscale[h];
    float sA[16], sB[16];
#pragma unroll
    for (int t = 0; t < 8; t++) {
        float2 cA = *(const float2*)&scomb[rowA * STC + t * 8 + 2 * cq];
        float2 cB = *(const float2*)&scomb[(rowA + 8) * STC + t * 8 + 2 * cq];
        sA[2 * t]     = fmaf(D[t][0], scale, cA.x);
        sA[2 * t + 1] = fmaf(D[t][1], scale, cA.y);
        sB[2 * t]     = fmaf(D[t][2], scale, cB.x);
        sB[2 * t + 1] = fmaf(D[t][3], scale, cB.y);
    }
    float mxA = -1e30f, mxB = -1e30f;
#pragma unroll
    for (int c = 0; c < 16; c++) { mxA = fmaxf(mxA, sA[c]); mxB = fmaxf(mxB, sB[c]); }
    mxA = fmaxf(mxA, __shfl_xor_sync(0xffffffffu, mxA, 1));
    mxA = fmaxf(mxA, __shfl_xor_sync(0xffffffffu, mxA, 2));
    mxB = fmaxf(mxB, __shfl_xor_sync(0xffffffffu, mxB, 1));
    mxB = fmaxf(mxB, __shfl_xor_sync(0xffffffffu, mxB, 2));
    float smA = 0.f, smB = 0.f;
#pragma unroll
    for (int c = 0; c < 16; c++) {
        sA[c] = __expf(sA[c] - mxA); smA += sA[c];
        sB[c] = __expf(sB[c] - mxB); smB += sB[c];
    }
    smA += __shfl_xor_sync(0xffffffffu, smA, 1);
    smA += __shfl_xor_sync(0xffffffffu, smA, 2);
    smB += __shfl_xor_sync(0xffffffffu, smB, 1);
    smB += __shfl_xor_sync(0xffffffffu, smB, 2);
    const float rinvA = 1.f / smA, rinvB = 1.f / smB;
#pragma unroll
    for (int c = 0; c < 16; c++) { sA[c] *= rinvA; sB[c] *= rinvB; }

    // ---- P -> bf16 hi/lo A-fragments (in registers; D-frag layout == A-frag) ----
    unsigned ph[4][4], pl[4][4];
#pragma unroll
    for (int ks = 0; ks < 4; ks++) {
        ph[ks][0] = pack2(sA[4 * ks], sA[4 * ks + 1]);
        ph[ks][1] = pack2(sB[4 * ks], sB[4 * ks + 1]);
        ph[ks][2] = pack2(sA[4 * ks + 2], sA[4 * ks + 3]);
        ph[ks][3] = pack2(sB[4 * ks + 2], sB[4 * ks + 3]);
        pl[ks][0] = pack2(sA[4 * ks] - bflo(ph[ks][0]),     sA[4 * ks + 1] - bfhi(ph[ks][0]));
        pl[ks][1] = pack2(sB[4 * ks] - bflo(ph[ks][1]),     sB[4 * ks + 1] - bfhi(ph[ks][1]));
        pl[ks][2] = pack2(sA[4 * ks + 2] - bflo(ph[ks][2]), sA[4 * ks + 3] - bfhi(ph[ks][2]));
        pl[ks][3] = pack2(sB[4 * ks + 2] - bflo(ph[ks][3]), sB[4 * ks + 3] - bfhi(ph[ks][3]));
    }

    // ---- PV: O[16 x 32] per warp; B = V from [d][m] smem ----
    float O[4][4];
#pragma unroll
    for (int t = 0; t < 4; t++)
#pragma unroll
        for (int c = 0; c < 4; c++) O[t][c] = 0.f;

#pragma unroll
    for (int dt = 0; dt < 4; dt++) {
#pragma unroll
        for (int ks = 0; ks < 4; ks++) {
            const unsigned* vp = svw + (dt * 8 + r) * STV + 8 * ks + cq;
            unsigned bh0 = vp[0], bh1 = vp[4];
            unsigned bl0 = vp[32], bl1 = vp[36];
            MMA(O[dt], ph[ks], bh0, bh1);
            MMA(O[dt], ph[ks], bl0, bl1);
            MMA(O[dt], pl[ks], bh0, bh1);
        }
    }

    // ---- store O: token rows rowA (i=2*wrp, j=r) and rowA+8 (i=2*wrp+1, j=r) ----
    const int yA = (y0 + 2 * wrp) & 255;
    const int yB = (y0 + 2 * wrp + 1) & 255;
    const int xj = (x0 + r) & 255;
#pragma unroll
    for (int dt = 0; dt < 4; dt++) {
        const int d = dt * 8 + 2 * cq;
        out[(chbase + d) * HW + yA * 256 + xj]     = O[dt][0];
        out[(chbase + d + 1) * HW + yA * 256 + xj] = O[dt][1];
        out[(chbase + d) * HW + yB * 256 + xj]     = O[dt][2];
        out[(chbase + d + 1) * HW + yB * 256 + xj] = O[dt][3];
    }
}

// ---------------------------------------------------------------------------
extern "C" void kernel_launch(void* const* d_in, const int* in_sizes, int n_in,
                              void* d_out, int out_size) {
    const float* qkv         = (const float*)d_in[0];
    const float* table       = (const float*)d_in[1];
    const int*   index       = (const int*)  d_in[2];
    const float* mask        = (const float*)d_in[3];
    const float* logit_scale = (const float*)d_in[4];
    const float* w1          = (const float*)d_in[5];
    const float* b1          = (const float*)d_in[6];
    const float* w2          = (const float*)d_in[7];
    float* out = (float*)d_out;

    cudaFuncSetAttribute(win_attn_kernel,
                         cudaFuncAttributePreferredSharedMemoryCarveout, 100);

    bias_mlp_kernel<<<TBL, 128>>>(table, logit_scale, w1, b1, w2);
    bias_gather_kernel<<<96, 256>>>(index);

    float* d_bias = nullptr;
    cudaGetSymbolAddress((void**)&d_bias, g_bias);
    win_attn_kernel<<<2 * 1024 * NH, 128>>>(qkv, mask, d_bias, out);
    (void)in_sizes; (void)n_in; (void)out_size;
}

// round 9
// speedup vs baseline: 1.1960x; 1.0170x over previous
#include <cuda_runtime.h>
#include <cuda_bf16.h>

#define NH 6
#define HD 32
#define NTOK 64
#define HIDDEN 512
#define TBL 225
#define HW 65536

// Q/K smem: [64 rows][36 words]; words 0..15 = k-pair hi words, 16..31 = lo, 4 pad.
#define STQK 36
// V smem: [32 rows][68 words]; words 0..31 = m-pair hi, 32..63 = lo, 4 pad.
#define STV 68
#define LOG2E 1.4426950408889634f

// m16n8k16 row.col f32.bf16.bf16.f32
#define MMA(D, A, b0, b1) \
    asm("mma.sync.aligned.m16n8k16.row.col.f32.bf16.bf16.f32 " \
        "{%0,%1,%2,%3},{%4,%5,%6,%7},{%8,%9},{%0,%1,%2,%3};" \
        : "+f"(D[0]), "+f"(D[1]), "+f"(D[2]), "+f"(D[3]) \
        : "r"(A[0]), "r"(A[1]), "r"(A[2]), "r"(A[3]), "r"(b0), "r"(b1))

__device__ __forceinline__ unsigned pack2(float lo, float hi) {
    unsigned r;
    asm("cvt.rn.bf16x2.f32 %0, %1, %2;" : "=r"(r) : "f"(hi), "f"(lo));
    return r;  // low half = lo, high half = hi
}
__device__ __forceinline__ float bflo(unsigned w) { return __uint_as_float(w << 16); }
__device__ __forceinline__ float bfhi(unsigned w) { return __uint_as_float(w & 0xffff0000u); }
__device__ __forceinline__ float ex2f(float x) {
    float y;
    asm("ex2.approx.ftz.f32 %0, %1;" : "=f"(y) : "f"(x));
    return y;
}

// device-global scratch (no allocations allowed)
__device__ float g_bt[TBL * NH];
__device__ float g_hscale[NH];       // exp(min(ls,max)) * rsqrt(hd) * log2e
__device__ float g_bias[NH * NTOK * NTOK];  // 16*sigmoid(..) * log2e

// ---------------------------------------------------------------------------
// Kernel 0a: CPB MLP, one block per table row (225 blocks) + head scales.
// ---------------------------------------------------------------------------
__global__ void __launch_bounds__(128) bias_mlp_kernel(
    const float* __restrict__ table,
    const float* __restrict__ logit_scale,
    const float* __restrict__ w1,
    const float* __restrict__ b1,
    const float* __restrict__ w2) {
    const int row = blockIdx.x;
    const int tid = threadIdx.x;

    if (row == 0 && tid < NH) {
        const float LOGIT_MAX = 4.605170185988091368f; // log(100)
        g_hscale[tid] = expf(fminf(logit_scale[tid], LOGIT_MAX)) * rsqrtf((float)HD) * LOG2E;
    }

    const float t0 = table[row * 2 + 0];
    const float t1 = table[row * 2 + 1];
    float acc[NH];
#pragma unroll
    for (int h = 0; h < NH; h++) acc[h] = 0.f;

    for (int j = tid; j < HIDDEN; j += 128) {
        float hv = fmaf(t0, w1[j], fmaf(t1, w1[HIDDEN + j], b1[j]));
        hv = fmaxf(hv, 0.f);
#pragma unroll
        for (int h = 0; h < NH; h++) acc[h] = fmaf(hv, w2[j * NH + h], acc[h]);
    }

#pragma unroll
    for (int h = 0; h < NH; h++) {
#pragma unroll
        for (int o = 16; o > 0; o >>= 1)
            acc[h] += __shfl_xor_sync(0xffffffffu, acc[h], o);
    }
    __shared__ float red[4][NH];
    const int warp = tid >> 5;
    if ((tid & 31) == 0) {
#pragma unroll
        for (int h = 0; h < NH; h++) red[warp][h] = acc[h];
    }
    __syncthreads();
    if (tid == 0) {
#pragma unroll
        for (int h = 0; h < NH; h++)
            g_bt[row * NH + h] = red[0][h] + red[1][h] + red[2][h] + red[3][h];
    }
}

// ---------------------------------------------------------------------------
// Kernel 0b: expand bias -> g_bias[h][n][m] = 16*sigmoid(bt[idx][h]) * log2e
// ---------------------------------------------------------------------------
__global__ void bias_gather_kernel(const int* __restrict__ index) {
    int gid = blockIdx.x * blockDim.x + threadIdx.x;
    if (gid >= NH * NTOK * NTOK) return;
    int h = gid >> 12;
    int nm = gid & 4095;
    int r = index[nm];
    float bv = g_bt[r * NH + h];
    g_bias[gid] = (16.f / (1.f + __expf(-bv))) * LOG2E;
}

// ---------------------------------------------------------------------------
// Main kernel: one CTA per (window, head). 128 threads (4 warps), 5 CTAs/SM.
//  bf16x3 split mma.sync; pair-packed staging; log2-domain softmax in frags.
// ---------------------------------------------------------------------------
__global__ void __launch_bounds__(128, 5) win_attn_kernel(
    const float* __restrict__ qkv,
    const float* __restrict__ mask,
    const float* __restrict__ bias,
    float* __restrict__ out)
{
    __shared__ __align__(16) unsigned sqw[NTOK * STQK];   // Q bf16 hi/lo
    __shared__ __align__(16) unsigned skw[NTOK * STQK];   // K bf16 hi/lo
    __shared__ __align__(16) unsigned svw[HD * STV];      // V bf16 hi/lo, [d][m]

    const int tid = threadIdx.x;
    const int bid = blockIdx.x;
    const int h = bid % NH;
    const int b_ = bid / NH;           // 0..2047
    const int b = b_ >> 10;            // batch
    const int w = b_ & 1023;           // window id within image
    const int wy = w >> 5, wx = w & 31;
    // roll(-4,-4): window pixel (i,j) <- original ((wy*8+i+4)&255, (wx*8+j+4)&255)
    const int y0 = wy * 8 + 4;
    const int x0 = wx * 8 + 4;

    // channel = t*384 + b*192 + h*32 + d   (qkv is (3,B,192,H,W))
    const int chbase = b * 192 + h * 32;

    const float* mask_w = mask + w * 4096;
    const float* bias_h = bias + h * 4096;

    // ---- stage Q,K: each unit = (tensor, k-pair, token-quad) -> packed words ----
#pragma unroll
    for (int l = 0; l < 4; l++) {
        int u = tid + l * 128;          // 0..511
        int t = u >> 8;                 // 0 = q, 1 = k
        int rem = u & 255;
        int kp = rem >> 4;              // k-pair 0..15
        int q16 = rem & 15;
        int i = q16 >> 1;
        int j0 = (q16 & 1) << 2;
        int y = (y0 + i) & 255;
        int x = (x0 + j0) & 255;        // 4-aligned, never splits across wrap
        const float* basep = qkv + (chbase + t * 384 + 2 * kp) * HW + y * 256 + x;
        float4 v0 = *(const float4*)basep;          // channel 2*kp
        float4 v1 = *(const float4*)(basep + HW);   // channel 2*kp+1
        unsigned* rowbase = (t == 0) ? sqw : skw;
        int n = i * 8 + j0;
        float a0[4] = {v0.x, v0.y, v0.z, v0.w};
        float a1[4] = {v1.x, v1.y, v1.z, v1.w};
#pragma unroll
        for (int e = 0; e < 4; e++) {
            unsigned hw_ = pack2(a0[e], a1[e]);
            unsigned lw_ = pack2(a0[e] - bflo(hw_), a1[e] - bfhi(hw_));
            rowbase[(n + e) * STQK + kp] = hw_;
            rowbase[(n + e) * STQK + 16 + kp] = lw_;
        }
    }
    // ---- stage V -> [d][m] packed m-pair words ----
#pragma unroll
    for (int l = 0; l < 4; l++) {
        int u = tid + l * 128;          // 0..511
        int d = u >> 4;                 // 0..31
        int q16 = u & 15;
        int i = q16 >> 1;
        int j0 = (q16 & 1) << 2;
        int y = (y0 + i) & 255;
        int x = (x0 + j0) & 255;
        float4 v = *(const float4*)(qkv + (chbase + 768 + d) * HW + y * 256 + x);
        int n = i * 8 + j0;
        unsigned h0 = pack2(v.x, v.y);
        unsigned h1 = pack2(v.z, v.w);
        unsigned l0 = pack2(v.x - bflo(h0), v.y - bfhi(h0));
        unsigned l1 = pack2(v.z - bflo(h1), v.w - bfhi(h1));
        *(uint2*)&svw[d * STV + (n >> 1)] = make_uint2(h0, h1);
        *(uint2*)&svw[d * STV + 32 + (n >> 1)] = make_uint2(l0, l1);
    }
    __syncthreads();

    const int lane = tid & 31;
    const int wrp = tid >> 5;           // warp owns S rows 16*wrp..16*wrp+15
    const int r = lane >> 2;            // groupID
    const int cq = lane & 3;            // threadID in group
    const int rowA = wrp * 16 + r;      // global token row (half A); half B = +8

    // ---- QK^T: A fragments (Q) hoisted; loop 8 n-tiles x 2 k-steps x 3 splits ----
    unsigned ah[2][4], al[2][4];
#pragma unroll
    for (int ks = 0; ks < 2; ks++) {
        const unsigned* q0 = sqw + rowA * STQK + 8 * ks + cq;
        const unsigned* q1 = sqw + (rowA + 8) * STQK + 8 * ks + cq;
        ah[ks][0] = q0[0];  ah[ks][1] = q1[0];  ah[ks][2] = q0[4];  ah[ks][3] = q1[4];
        al[ks][0] = q0[16]; al[ks][1] = q1[16]; al[ks][2] = q0[20]; al[ks][3] = q1[20];
    }

    float D[8][4];
#pragma unroll
    for (int t = 0; t < 8; t++)
#pragma unroll
        for (int c = 0; c < 4; c++) D[t][c] = 0.f;

#pragma unroll
    for (int nt = 0; nt < 8; nt++) {
#pragma unroll
        for (int ks = 0; ks < 2; ks++) {
            const unsigned* kp = skw + (nt * 8 + r) * STQK + 8 * ks + cq;
            unsigned bh0 = kp[0], bh1 = kp[4];
            unsigned bl0 = kp[16], bl1 = kp[20];
            MMA(D[nt], ah[ks], bh0, bh1);
            MMA(D[nt], ah[ks], bl0, bl1);
            MMA(D[nt], al[ks], bh0, bh1);
        }
    }

    // ---- softmax in fragments, log2 domain; bias/mask read direct ----
    const float scale2 = g_hscale[h];   // includes log2e
    float sA[16], sB[16];
#pragma unroll
    for (int t = 0; t < 8; t++) {
        float2 bA = *(const float2*)(bias_h + rowA * 64 + t * 8 + 2 * cq);
        float2 mA = *(const float2*)(mask_w + rowA * 64 + t * 8 + 2 * cq);
        float2 bB = *(const float2*)(bias_h + (rowA + 8) * 64 + t * 8 + 2 * cq);
        float2 mB = *(const float2*)(mask_w + (rowA + 8) * 64 + t * 8 + 2 * cq);
        sA[2 * t]     = fmaf(D[t][0], scale2, fmaf(mA.x, LOG2E, bA.x));
        sA[2 * t + 1] = fmaf(D[t][1], scale2, fmaf(mA.y, LOG2E, bA.y));
        sB[2 * t]     = fmaf(D[t][2], scale2, fmaf(mB.x, LOG2E, bB.x));
        sB[2 * t + 1] = fmaf(D[t][3], scale2, fmaf(mB.y, LOG2E, bB.y));
    }
    float mxA = -1e30f, mxB = -1e30f;
#pragma unroll
    for (int c = 0; c < 16; c++) { mxA = fmaxf(mxA, sA[c]); mxB = fmaxf(mxB, sB[c]); }
    mxA = fmaxf(mxA, __shfl_xor_sync(0xffffffffu, mxA, 1));
    mxA = fmaxf(mxA, __shfl_xor_sync(0xffffffffu, mxA, 2));
    mxB = fmaxf(mxB, __shfl_xor_sync(0xffffffffu, mxB, 1));
    mxB = fmaxf(mxB, __shfl_xor_sync(0xffffffffu, mxB, 2));
    float smA = 0.f, smB = 0.f;
#pragma unroll
    for (int c = 0; c < 16; c++) {
        sA[c] = ex2f(sA[c] - mxA); smA += sA[c];
        sB[c] = ex2f(sB[c] - mxB); smB += sB[c];
    }
    smA += __shfl_xor_sync(0xffffffffu, smA, 1);
    smA += __shfl_xor_sync(0xffffffffu, smA, 2);
    smB += __shfl_xor_sync(0xffffffffu, smB, 1);
    smB += __shfl_xor_sync(0xffffffffu, smB, 2);
    const float rinvA = 1.f / smA, rinvB = 1.f / smB;
    // P left unnormalized; 1/sum folded into the O store.

    // ---- P -> bf16 hi/lo A-fragments (in registers; D-frag layout == A-frag) ----
    unsigned ph[4][4], pl[4][4];
#pragma unroll
    for (int ks = 0; ks < 4; ks++) {
        ph[ks][0] = pack2(sA[4 * ks], sA[4 * ks + 1]);
        ph[ks][1] = pack2(sB[4 * ks], sB[4 * ks + 1]);
        ph[ks][2] = pack2(sA[4 * ks + 2], sA[4 * ks + 3]);
        ph[ks][3] = pack2(sB[4 * ks + 2], sB[4 * ks + 3]);
        pl[ks][0] = pack2(sA[4 * ks] - bflo(ph[ks][0]),     sA[4 * ks + 1] - bfhi(ph[ks][0]));
        pl[ks][1] = pack2(sB[4 * ks] - bflo(ph[ks][1]),     sB[4 * ks + 1] - bfhi(ph[ks][1]));
        pl[ks][2] = pack2(sA[4 * ks + 2] - bflo(ph[ks][2]), sA[4 * ks + 3] - bfhi(ph[ks][2]));
        pl[ks][3] = pack2(sB[4 * ks + 2] - bflo(ph[ks][3]), sB[4 * ks + 3] - bfhi(ph[ks][3]));
    }

    // ---- PV: O[16 x 32] per warp; B = V from [d][m] smem ----
    float O[4][4];
#pragma unroll
    for (int t = 0; t < 4; t++)
#pragma unroll
        for (int c = 0; c < 4; c++) O[t][c] = 0.f;

#pragma unroll
    for (int dt = 0; dt < 4; dt++) {
#pragma unroll
        for (int ks = 0; ks < 4; ks++) {
            const unsigned* vp = svw + (dt * 8 + r) * STV + 8 * ks + cq;
            unsigned bh0 = vp[0], bh1 = vp[4];
            unsigned bl0 = vp[32], bl1 = vp[36];
            MMA(O[dt], ph[ks], bh0, bh1);
            MMA(O[dt], ph[ks], bl0, bl1);
            MMA(O[dt], pl[ks], bh0, bh1);
        }
    }

    // ---- store O (normalize by 1/sum here) ----
    const int yA = (y0 + 2 * wrp) & 255;
    const int yB = (y0 + 2 * wrp + 1) & 255;
    const int xj = (x0 + r) & 255;
#pragma unroll
    for (int dt = 0; dt < 4; dt++) {
        const int d = dt * 8 + 2 * cq;
        out[(chbase + d) * HW + yA * 256 + xj]     = O[dt][0] * rinvA;
        out[(chbase + d + 1) * HW + yA * 256 + xj] = O[dt][1] * rinvA;
        out[(chbase + d) * HW + yB * 256 + xj]     = O[dt][2] * rinvB;
        out[(chbase + d + 1) * HW + yB * 256 + xj] = O[dt][3] * rinvB;
    }
}

// ---------------------------------------------------------------------------
extern "C" void kernel_launch(void* const* d_in, const int* in_sizes, int n_in,
                              void* d_out, int out_size) {
    const float* qkv         = (const float*)d_in[0];
    const float* table       = (const float*)d_in[1];
    const int*   index       = (const int*)  d_in[2];
    const float* mask        = (const float*)d_in[3];
    const float* logit_scale = (const float*)d_in[4];
    const float* w1          = (const float*)d_in[5];
    const float* b1          = (const float*)d_in[6];
    const float* w2          = (const float*)d_in[7];
    float* out = (float*)d_out;

    cudaFuncSetAttribute(win_attn_kernel,
                         cudaFuncAttributePreferredSharedMemoryCarveout, 100);

    bias_mlp_kernel<<<TBL, 128>>>(table, logit_scale, w1, b1, w2);
    bias_gather_kernel<<<96, 256>>>(index);

    float* d_bias = nullptr;
    cudaGetSymbolAddress((void**)&d_bias, g_bias);
    win_attn_kernel<<<2 * 1024 * NH, 128>>>(qkv, mask, d_bias, out);
    (void)in_sizes; (void)n_in; (void)out_size;
}

// round 10
// speedup vs baseline: 1.2099x; 1.0116x over previous
#include <cuda_runtime.h>
#include <cuda_bf16.h>

#define NH 6
#define HD 32
#define NTOK 64
#define HIDDEN 512
#define TBL 225
#define HW 65536

// Q/K smem: [64 rows][36 words]; words 0..15 = k-pair hi words, 16..31 = lo, 4 pad.
#define STQK 36
// V smem: [32 rows][68 words]; words 0..31 = m-pair hi, 32..63 = lo, 4 pad.
#define STV 68
#define LOG2E 1.4426950408889634f

// m16n8k16 row.col f32.bf16.bf16.f32
#define MMA(D, A, b0, b1) \
    asm("mma.sync.aligned.m16n8k16.row.col.f32.bf16.bf16.f32 " \
        "{%0,%1,%2,%3},{%4,%5,%6,%7},{%8,%9},{%0,%1,%2,%3};" \
        : "+f"(D[0]), "+f"(D[1]), "+f"(D[2]), "+f"(D[3]) \
        : "r"(A[0]), "r"(A[1]), "r"(A[2]), "r"(A[3]), "r"(b0), "r"(b1))

__device__ __forceinline__ unsigned pack2(float lo, float hi) {
    unsigned r;
    asm("cvt.rn.bf16x2.f32 %0, %1, %2;" : "=r"(r) : "f"(hi), "f"(lo));
    return r;  // low half = lo, high half = hi
}
__device__ __forceinline__ float bflo(unsigned w) { return __uint_as_float(w << 16); }
__device__ __forceinline__ float bfhi(unsigned w) { return __uint_as_float(w & 0xffff0000u); }
__device__ __forceinline__ float ex2f(float x) {
    float y;
    asm("ex2.approx.ftz.f32 %0, %1;" : "=f"(y) : "f"(x));
    return y;
}

// device-global scratch (no allocations allowed)
__device__ float g_bt[TBL * NH];
__device__ float g_hscale[NH];       // exp(min(ls,max)) * rsqrt(hd) * log2e
__device__ float g_bias[NH * NTOK * NTOK];  // 16*sigmoid(..) * log2e

// ---------------------------------------------------------------------------
// Kernel 0a: CPB MLP, one block per table row (225 blocks) + head scales.
// ---------------------------------------------------------------------------
__global__ void __launch_bounds__(128) bias_mlp_kernel(
    const float* __restrict__ table,
    const float* __restrict__ logit_scale,
    const float* __restrict__ w1,
    const float* __restrict__ b1,
    const float* __restrict__ w2) {
    const int row = blockIdx.x;
    const int tid = threadIdx.x;

    if (row == 0 && tid < NH) {
        const float LOGIT_MAX = 4.605170185988091368f; // log(100)
        g_hscale[tid] = expf(fminf(logit_scale[tid], LOGIT_MAX)) * rsqrtf((float)HD) * LOG2E;
    }

    const float t0 = table[row * 2 + 0];
    const float t1 = table[row * 2 + 1];
    float acc[NH];
#pragma unroll
    for (int h = 0; h < NH; h++) acc[h] = 0.f;

    for (int j = tid; j < HIDDEN; j += 128) {
        float hv = fmaf(t0, w1[j], fmaf(t1, w1[HIDDEN + j], b1[j]));
        hv = fmaxf(hv, 0.f);
#pragma unroll
        for (int h = 0; h < NH; h++) acc[h] = fmaf(hv, w2[j * NH + h], acc[h]);
    }

#pragma unroll
    for (int h = 0; h < NH; h++) {
#pragma unroll
        for (int o = 16; o > 0; o >>= 1)
            acc[h] += __shfl_xor_sync(0xffffffffu, acc[h], o);
    }
    __shared__ float red[4][NH];
    const int warp = tid >> 5;
    if ((tid & 31) == 0) {
#pragma unroll
        for (int h = 0; h < NH; h++) red[warp][h] = acc[h];
    }
    __syncthreads();
    if (tid == 0) {
#pragma unroll
        for (int h = 0; h < NH; h++)
            g_bt[row * NH + h] = red[0][h] + red[1][h] + red[2][h] + red[3][h];
    }
}

// ---------------------------------------------------------------------------
// Kernel 0b: expand bias -> g_bias[h][n][m] = 16*sigmoid(bt[idx][h]) * log2e
// ---------------------------------------------------------------------------
__global__ void bias_gather_kernel(const int* __restrict__ index) {
    int gid = blockIdx.x * blockDim.x + threadIdx.x;
    if (gid >= NH * NTOK * NTOK) return;
    int h = gid >> 12;
    int nm = gid & 4095;
    int r = index[nm];
    float bv = g_bt[r * NH + h];
    g_bias[gid] = (16.f / (1.f + __expf(-bv))) * LOG2E;
}

// ---------------------------------------------------------------------------
// Main kernel: one CTA per (window, head). 128 threads (4 warps), 6 CTAs/SM.
//  bf16x3 split mma.sync; softmax in place in D-fragments; progressive P pack.
// ---------------------------------------------------------------------------
__global__ void __launch_bounds__(128, 6) win_attn_kernel(
    const float* __restrict__ qkv,
    const float* __restrict__ mask,
    const float* __restrict__ bias,
    float* __restrict__ out)
{
    __shared__ __align__(16) unsigned sqw[NTOK * STQK];   // Q bf16 hi/lo
    __shared__ __align__(16) unsigned skw[NTOK * STQK];   // K bf16 hi/lo
    __shared__ __align__(16) unsigned svw[HD * STV];      // V bf16 hi/lo, [d][m]

    const int tid = threadIdx.x;
    const int bid = blockIdx.x;
    const int h = bid % NH;
    const int b_ = bid / NH;           // 0..2047
    const int b = b_ >> 10;            // batch
    const int w = b_ & 1023;           // window id within image
    const int wy = w >> 5, wx = w & 31;
    // roll(-4,-4): window pixel (i,j) <- original ((wy*8+i+4)&255, (wx*8+j+4)&255)
    const int y0 = wy * 8 + 4;
    const int x0 = wx * 8 + 4;

    // channel = t*384 + b*192 + h*32 + d   (qkv is (3,B,192,H,W))
    const int chbase = b * 192 + h * 32;

    const float* mask_w = mask + w * 4096;
    const float* bias_h = bias + h * 4096;

    // ---- stage Q,K: each unit = (tensor, k-pair, token-quad) -> packed words ----
#pragma unroll
    for (int l = 0; l < 4; l++) {
        int u = tid + l * 128;          // 0..511
        int t = u >> 8;                 // 0 = q, 1 = k
        int rem = u & 255;
        int kp = rem >> 4;              // k-pair 0..15
        int q16 = rem & 15;
        int i = q16 >> 1;
        int j0 = (q16 & 1) << 2;
        int y = (y0 + i) & 255;
        int x = (x0 + j0) & 255;        // 4-aligned, never splits across wrap
        const float* basep = qkv + (chbase + t * 384 + 2 * kp) * HW + y * 256 + x;
        float4 v0 = *(const float4*)basep;          // channel 2*kp
        float4 v1 = *(const float4*)(basep + HW);   // channel 2*kp+1
        unsigned* rowbase = (t == 0) ? sqw : skw;
        int n = i * 8 + j0;
        float a0[4] = {v0.x, v0.y, v0.z, v0.w};
        float a1[4] = {v1.x, v1.y, v1.z, v1.w};
#pragma unroll
        for (int e = 0; e < 4; e++) {
            unsigned hw_ = pack2(a0[e], a1[e]);
            unsigned lw_ = pack2(a0[e] - bflo(hw_), a1[e] - bfhi(hw_));
            rowbase[(n + e) * STQK + kp] = hw_;
            rowbase[(n + e) * STQK + 16 + kp] = lw_;
        }
    }
    // ---- stage V -> [d][m] packed m-pair words ----
#pragma unroll
    for (int l = 0; l < 4; l++) {
        int u = tid + l * 128;          // 0..511
        int d = u >> 4;                 // 0..31
        int q16 = u & 15;
        int i = q16 >> 1;
        int j0 = (q16 & 1) << 2;
        int y = (y0 + i) & 255;
        int x = (x0 + j0) & 255;
        float4 v = *(const float4*)(qkv + (chbase + 768 + d) * HW + y * 256 + x);
        int n = i * 8 + j0;
        unsigned h0 = pack2(v.x, v.y);
        unsigned h1 = pack2(v.z, v.w);
        unsigned l0 = pack2(v.x - bflo(h0), v.y - bfhi(h0));
        unsigned l1 = pack2(v.z - bflo(h1), v.w - bfhi(h1));
        *(uint2*)&svw[d * STV + (n >> 1)] = make_uint2(h0, h1);
        *(uint2*)&svw[d * STV + 32 + (n >> 1)] = make_uint2(l0, l1);
    }
    __syncthreads();

    const int lane = tid & 31;
    const int wrp = tid >> 5;           // warp owns S rows 16*wrp..16*wrp+15
    const int r = lane >> 2;            // groupID
    const int cq = lane & 3;            // threadID in group
    const int rowA = wrp * 16 + r;      // global token row (half A); half B = +8

    // ---- QK^T: A fragments (Q) hoisted; loop 8 n-tiles x 2 k-steps x 3 splits ----
    unsigned ah[2][4], al[2][4];
#pragma unroll
    for (int ks = 0; ks < 2; ks++) {
        const unsigned* q0 = sqw + rowA * STQK + 8 * ks + cq;
        const unsigned* q1 = sqw + (rowA + 8) * STQK + 8 * ks + cq;
        ah[ks][0] = q0[0];  ah[ks][1] = q1[0];  ah[ks][2] = q0[4];  ah[ks][3] = q1[4];
        al[ks][0] = q0[16]; al[ks][1] = q1[16]; al[ks][2] = q0[20]; al[ks][3] = q1[20];
    }

    float D[8][4];
#pragma unroll
    for (int t = 0; t < 8; t++)
#pragma unroll
        for (int c = 0; c < 4; c++) D[t][c] = 0.f;

#pragma unroll
    for (int nt = 0; nt < 8; nt++) {
#pragma unroll
        for (int ks = 0; ks < 2; ks++) {
            const unsigned* kp = skw + (nt * 8 + r) * STQK + 8 * ks + cq;
            unsigned bh0 = kp[0], bh1 = kp[4];
            unsigned bl0 = kp[16], bl1 = kp[20];
            MMA(D[nt], ah[ks], bh0, bh1);
            MMA(D[nt], ah[ks], bl0, bl1);
            MMA(D[nt], al[ks], bh0, bh1);
        }
    }

    // ---- softmax IN PLACE in D, log2 domain ----
    // D[t][0..1] -> row rowA cols t*8+2cq(+1); D[t][2..3] -> row rowA+8.
    const float scale2 = g_hscale[h];   // includes log2e
    const float* bA_p = bias_h + rowA * 64 + 2 * cq;
    const float* mA_p = mask_w + rowA * 64 + 2 * cq;
#pragma unroll
    for (int t = 0; t < 8; t++) {
        float2 bA = *(const float2*)(bA_p + t * 8);
        float2 mA = *(const float2*)(mA_p + t * 8);
        float2 bB = *(const float2*)(bA_p + 512 + t * 8);   // (rowA+8)*64
        float2 mB = *(const float2*)(mA_p + 512 + t * 8);
        D[t][0] = fmaf(D[t][0], scale2, fmaf(mA.x, LOG2E, bA.x));
        D[t][1] = fmaf(D[t][1], scale2, fmaf(mA.y, LOG2E, bA.y));
        D[t][2] = fmaf(D[t][2], scale2, fmaf(mB.x, LOG2E, bB.x));
        D[t][3] = fmaf(D[t][3], scale2, fmaf(mB.y, LOG2E, bB.y));
    }
    float mxA = -1e30f, mxB = -1e30f;
#pragma unroll
    for (int t = 0; t < 8; t++) {
        mxA = fmaxf(mxA, fmaxf(D[t][0], D[t][1]));
        mxB = fmaxf(mxB, fmaxf(D[t][2], D[t][3]));
    }
    mxA = fmaxf(mxA, __shfl_xor_sync(0xffffffffu, mxA, 1));
    mxA = fmaxf(mxA, __shfl_xor_sync(0xffffffffu, mxA, 2));
    mxB = fmaxf(mxB, __shfl_xor_sync(0xffffffffu, mxB, 1));
    mxB = fmaxf(mxB, __shfl_xor_sync(0xffffffffu, mxB, 2));

    // progressive: exp, sum, pack P (hi/lo) per k-step pair; D dies as ph/pl born
    unsigned ph[4][4], pl[4][4];
    float smA = 0.f, smB = 0.f;
#pragma unroll
    for (int ks = 0; ks < 4; ks++) {
        float e00 = ex2f(D[2 * ks][0] - mxA);
        float e01 = ex2f(D[2 * ks][1] - mxA);
        float e02 = ex2f(D[2 * ks][2] - mxB);
        float e03 = ex2f(D[2 * ks][3] - mxB);
        float e10 = ex2f(D[2 * ks + 1][0] - mxA);
        float e11 = ex2f(D[2 * ks + 1][1] - mxA);
        float e12 = ex2f(D[2 * ks + 1][2] - mxB);
        float e13 = ex2f(D[2 * ks + 1][3] - mxB);
        smA += e00 + e01 + e10 + e11;
        smB += e02 + e03 + e12 + e13;
        ph[ks][0] = pack2(e00, e01);
        ph[ks][1] = pack2(e02, e03);
        ph[ks][2] = pack2(e10, e11);
        ph[ks][3] = pack2(e12, e13);
        pl[ks][0] = pack2(e00 - bflo(ph[ks][0]), e01 - bfhi(ph[ks][0]));
        pl[ks][1] = pack2(e02 - bflo(ph[ks][1]), e03 - bfhi(ph[ks][1]));
        pl[ks][2] = pack2(e10 - bflo(ph[ks][2]), e11 - bfhi(ph[ks][2]));
        pl[ks][3] = pack2(e12 - bflo(ph[ks][3]), e13 - bfhi(ph[ks][3]));
    }
    smA += __shfl_xor_sync(0xffffffffu, smA, 1);
    smA += __shfl_xor_sync(0xffffffffu, smA, 2);
    smB += __shfl_xor_sync(0xffffffffu, smB, 1);
    smB += __shfl_xor_sync(0xffffffffu, smB, 2);
    const float rinvA = 1.f / smA, rinvB = 1.f / smB;
    // P left unnormalized; 1/sum folded into the O store.

    // ---- PV: O[16 x 32] per warp; B = V from [d][m] smem ----
    float O[4][4];
#pragma unroll
    for (int t = 0; t < 4; t++)
#pragma unroll
        for (int c = 0; c < 4; c++) O[t][c] = 0.f;

#pragma unroll
    for (int dt = 0; dt < 4; dt++) {
#pragma unroll
        for (int ks = 0; ks < 4; ks++) {
            const unsigned* vp = svw + (dt * 8 + r) * STV + 8 * ks + cq;
            unsigned bh0 = vp[0], bh1 = vp[4];
            unsigned bl0 = vp[32], bl1 = vp[36];
            MMA(O[dt], ph[ks], bh0, bh1);
            MMA(O[dt], ph[ks], bl0, bl1);
            MMA(O[dt], pl[ks], bh0, bh1);
        }
    }

    // ---- store O (normalize by 1/sum here) ----
    const int yA = (y0 + 2 * wrp) & 255;
    const int yB = (y0 + 2 * wrp + 1) & 255;
    const int xj = (x0 + r) & 255;
#pragma unroll
    for (int dt = 0; dt < 4; dt++) {
        const int d = dt * 8 + 2 * cq;
        out[(chbase + d) * HW + yA * 256 + xj]     = O[dt][0] * rinvA;
        out[(chbase + d + 1) * HW + yA * 256 + xj] = O[dt][1] * rinvA;
        out[(chbase + d) * HW + yB * 256 + xj]     = O[dt][2] * rinvB;
        out[(chbase + d + 1) * HW + yB * 256 + xj] = O[dt][3] * rinvB;
    }
}

// ---------------------------------------------------------------------------
extern "C" void kernel_launch(void* const* d_in, const int* in_sizes, int n_in,
                              void* d_out, int out_size) {
    const float* qkv         = (const float*)d_in[0];
    const float* table       = (const float*)d_in[1];
    const int*   index       = (const int*)  d_in[2];
    const float* mask        = (const float*)d_in[3];
    const float* logit_scale = (const float*)d_in[4];
    const float* w1          = (const float*)d_in[5];
    const float* b1          = (const float*)d_in[6];
    const float* w2          = (const float*)d_in[7];
    float* out = (float*)d_out;

    cudaFuncSetAttribute(win_attn_kernel,
                         cudaFuncAttributePreferredSharedMemoryCarveout, 100);

    bias_mlp_kernel<<<TBL, 128>>>(table, logit_scale, w1, b1, w2);
    bias_gather_kernel<<<96, 256>>>(index);

    float* d_bias = nullptr;
    cudaGetSymbolAddress((void**)&d_bias, g_bias);
    win_attn_kernel<<<2 * 1024 * NH, 128>>>(qkv, mask, d_bias, out);
    (void)in_sizes; (void)n_in; (void)out_size;
}

// round 11
// speedup vs baseline: 1.2738x; 1.0528x over previous
#include <cuda_runtime.h>
#include <cuda_bf16.h>

#define NH 6
#define HD 32
#define NTOK 64
#define HIDDEN 512
#define TBL 225
#define HW 65536

// Q/K smem row placement: row n at n*36 + ((n>>2)&15)   (words).
// words 0..15 of a row = k-pair hi, 16..31 = k-pair lo.
// -> staging stores conflict-free; fragment loads ~conflict-free.
#define STQK 36
#define SWQK(n) ((n) * STQK + (((n) >> 2) & 15))
// V smem: [32 rows][68 words]; words 0..31 = m-pair hi, 32..63 = lo, 4 pad.
#define STV 68
#define LOG2E 1.4426950408889634f

// m16n8k16 row.col f32.bf16.bf16.f32
#define MMA(D, A, b0, b1) \
    asm("mma.sync.aligned.m16n8k16.row.col.f32.bf16.bf16.f32 " \
        "{%0,%1,%2,%3},{%4,%5,%6,%7},{%8,%9},{%0,%1,%2,%3};" \
        : "+f"(D[0]), "+f"(D[1]), "+f"(D[2]), "+f"(D[3]) \
        : "r"(A[0]), "r"(A[1]), "r"(A[2]), "r"(A[3]), "r"(b0), "r"(b1))

__device__ __forceinline__ unsigned pack2(float lo, float hi) {
    unsigned r;
    asm("cvt.rn.bf16x2.f32 %0, %1, %2;" : "=r"(r) : "f"(hi), "f"(lo));
    return r;  // low half = lo, high half = hi
}
__device__ __forceinline__ float bflo(unsigned w) { return __uint_as_float(w << 16); }
__device__ __forceinline__ float bfhi(unsigned w) { return __uint_as_float(w & 0xffff0000u); }
__device__ __forceinline__ float ex2f(float x) {
    float y;
    asm("ex2.approx.ftz.f32 %0, %1;" : "=f"(y) : "f"(x));
    return y;
}

// device-global scratch (no allocations allowed)
__device__ float g_bt[TBL * NH];
__device__ float g_hscale[NH];       // exp(min(ls,max)) * rsqrt(hd) * log2e
__device__ float g_bias[NH * NTOK * NTOK];  // 16*sigmoid(..) * log2e

// ---------------------------------------------------------------------------
// Kernel 0a: CPB MLP, one block per table row (225 blocks) + head scales.
// ---------------------------------------------------------------------------
__global__ void __launch_bounds__(128) bias_mlp_kernel(
    const float* __restrict__ table,
    const float* __restrict__ logit_scale,
    const float* __restrict__ w1,
    const float* __restrict__ b1,
    const float* __restrict__ w2) {
    const int row = blockIdx.x;
    const int tid = threadIdx.x;

    if (row == 0 && tid < NH) {
        const float LOGIT_MAX = 4.605170185988091368f; // log(100)
        g_hscale[tid] = expf(fminf(logit_scale[tid], LOGIT_MAX)) * rsqrtf((float)HD) * LOG2E;
    }

    const float t0 = table[row * 2 + 0];
    const float t1 = table[row * 2 + 1];
    float acc[NH];
#pragma unroll
    for (int h = 0; h < NH; h++) acc[h] = 0.f;

    for (int j = tid; j < HIDDEN; j += 128) {
        float hv = fmaf(t0, w1[j], fmaf(t1, w1[HIDDEN + j], b1[j]));
        hv = fmaxf(hv, 0.f);
#pragma unroll
        for (int h = 0; h < NH; h++) acc[h] = fmaf(hv, w2[j * NH + h], acc[h]);
    }

#pragma unroll
    for (int h = 0; h < NH; h++) {
#pragma unroll
        for (int o = 16; o > 0; o >>= 1)
            acc[h] += __shfl_xor_sync(0xffffffffu, acc[h], o);
    }
    __shared__ float red[4][NH];
    const int warp = tid >> 5;
    if ((tid & 31) == 0) {
#pragma unroll
        for (int h = 0; h < NH; h++) red[warp][h] = acc[h];
    }
    __syncthreads();
    if (tid == 0) {
#pragma unroll
        for (int h = 0; h < NH; h++)
            g_bt[row * NH + h] = red[0][h] + red[1][h] + red[2][h] + red[3][h];
    }
}

// ---------------------------------------------------------------------------
// Kernel 0b: expand bias -> g_bias[h][n][m] = 16*sigmoid(bt[idx][h]) * log2e
// ---------------------------------------------------------------------------
__global__ void bias_gather_kernel(const int* __restrict__ index) {
    int gid = blockIdx.x * blockDim.x + threadIdx.x;
    if (gid >= NH * NTOK * NTOK) return;
    int h = gid >> 12;
    int nm = gid & 4095;
    int r = index[nm];
    float bv = g_bt[r * NH + h];
    g_bias[gid] = (16.f / (1.f + __expf(-bv))) * LOG2E;
}

// ---------------------------------------------------------------------------
// Main kernel: one CTA per (window, head). 128 threads (4 warps), 6 CTAs/SM.
//  bf16x3 split mma.sync; swizzled Q/K rows (conflict-free staging stores).
// ---------------------------------------------------------------------------
__global__ void __launch_bounds__(128, 6) win_attn_kernel(
    const float* __restrict__ qkv,
    const float* __restrict__ mask,
    const float* __restrict__ bias,
    float* __restrict__ out)
{
    __shared__ __align__(16) unsigned sqw[NTOK * STQK + 16];   // Q bf16 hi/lo
    __shared__ __align__(16) unsigned skw[NTOK * STQK + 16];   // K bf16 hi/lo
    __shared__ __align__(16) unsigned svw[HD * STV];           // V bf16 hi/lo, [d][m]

    const int tid = threadIdx.x;
    const int bid = blockIdx.x;
    const int h = bid % NH;
    const int b_ = bid / NH;           // 0..2047
    const int b = b_ >> 10;            // batch
    const int w = b_ & 1023;           // window id within image
    const int wy = w >> 5, wx = w & 31;
    // roll(-4,-4): window pixel (i,j) <- original ((wy*8+i+4)&255, (wx*8+j+4)&255)
    const int y0 = wy * 8 + 4;
    const int x0 = wx * 8 + 4;

    // channel = t*384 + b*192 + h*32 + d   (qkv is (3,B,192,H,W))
    const int chbase = b * 192 + h * 32;

    const float* mask_w = mask + w * 4096;
    const float* bias_h = bias + h * 4096;

    // ---- stage Q,K: each unit = (tensor, k-pair, token-quad) -> packed words ----
#pragma unroll
    for (int l = 0; l < 4; l++) {
        int u = tid + l * 128;          // 0..511
        int t = u >> 8;                 // 0 = q, 1 = k
        int rem = u & 255;
        int kp = rem >> 4;              // k-pair 0..15
        int q16 = rem & 15;
        int i = q16 >> 1;
        int j0 = (q16 & 1) << 2;
        int y = (y0 + i) & 255;
        int x = (x0 + j0) & 255;        // 4-aligned, never splits across wrap
        const float* basep = qkv + (chbase + t * 384 + 2 * kp) * HW + y * 256 + x;
        float4 v0 = *(const float4*)basep;          // channel 2*kp
        float4 v1 = *(const float4*)(basep + HW);   // channel 2*kp+1
        unsigned* rowbase = (t == 0) ? sqw : skw;
        int n = i * 8 + j0;
        float a0[4] = {v0.x, v0.y, v0.z, v0.w};
        float a1[4] = {v1.x, v1.y, v1.z, v1.w};
#pragma unroll
        for (int e = 0; e < 4; e++) {
            unsigned hw_ = pack2(a0[e], a1[e]);
            unsigned lw_ = pack2(a0[e] - bflo(hw_), a1[e] - bfhi(hw_));
            int ro = SWQK(n + e);
            rowbase[ro + kp] = hw_;
            rowbase[ro + 16 + kp] = lw_;
        }
    }
    // ---- stage V -> [d][m] packed m-pair words ----
#pragma unroll
    for (int l = 0; l < 4; l++) {
        int u = tid + l * 128;          // 0..511
        int d = u >> 4;                 // 0..31
        int q16 = u & 15;
        int i = q16 >> 1;
        int j0 = (q16 & 1) << 2;
        int y = (y0 + i) & 255;
        int x = (x0 + j0) & 255;
        float4 v = *(const float4*)(qkv + (chbase + 768 + d) * HW + y * 256 + x);
        int n = i * 8 + j0;
        unsigned h0 = pack2(v.x, v.y);
        unsigned h1 = pack2(v.z, v.w);
        unsigned l0 = pack2(v.x - bflo(h0), v.y - bfhi(h0));
        unsigned l1 = pack2(v.z - bflo(h1), v.w - bfhi(h1));
        *(uint2*)&svw[d * STV + (n >> 1)] = make_uint2(h0, h1);
        *(uint2*)&svw[d * STV + 32 + (n >> 1)] = make_uint2(l0, l1);
    }
    __syncthreads();

    const int lane = tid & 31;
    const int wrp = tid >> 5;           // warp owns S rows 16*wrp..16*wrp+15
    const int r = lane >> 2;            // groupID
    const int cq = lane & 3;            // threadID in group
    const int rowA = wrp * 16 + r;      // global token row (half A); half B = +8

    // ---- QK^T: A fragments (Q) hoisted; loop 8 n-tiles x 2 k-steps x 3 splits ----
    unsigned ah[2][4], al[2][4];
#pragma unroll
    for (int ks = 0; ks < 2; ks++) {
        const unsigned* q0 = sqw + SWQK(rowA) + 8 * ks + cq;
        const unsigned* q1 = sqw + SWQK(rowA + 8) + 8 * ks + cq;
        ah[ks][0] = q0[0];  ah[ks][1] = q1[0];  ah[ks][2] = q0[4];  ah[ks][3] = q1[4];
        al[ks][0] = q0[16]; al[ks][1] = q1[16]; al[ks][2] = q0[20]; al[ks][3] = q1[20];
    }

    float D[8][4];
#pragma unroll
    for (int t = 0; t < 8; t++)
#pragma unroll
        for (int c = 0; c < 4; c++) D[t][c] = 0.f;

#pragma unroll
    for (int nt = 0; nt < 8; nt++) {
#pragma unroll
        for (int ks = 0; ks < 2; ks++) {
            const unsigned* kp = skw + SWQK(nt * 8 + r) + 8 * ks + cq;
            unsigned bh0 = kp[0], bh1 = kp[4];
            unsigned bl0 = kp[16], bl1 = kp[20];
            MMA(D[nt], ah[ks], bh0, bh1);
            MMA(D[nt], ah[ks], bl0, bl1);
            MMA(D[nt], al[ks], bh0, bh1);
        }
    }

    // ---- softmax IN PLACE in D, log2 domain ----
    const float scale2 = g_hscale[h];   // includes log2e
    const float* bA_p = bias_h + rowA * 64 + 2 * cq;
    const float* mA_p = mask_w + rowA * 64 + 2 * cq;
#pragma unroll
    for (int t = 0; t < 8; t++) {
        float2 bA = *(const float2*)(bA_p + t * 8);
        float2 mA = *(const float2*)(mA_p + t * 8);
        float2 bB = *(const float2*)(bA_p + 512 + t * 8);   // (rowA+8)*64
        float2 mB = *(const float2*)(mA_p + 512 + t * 8);
        D[t][0] = fmaf(D[t][0], scale2, fmaf(mA.x, LOG2E, bA.x));
        D[t][1] = fmaf(D[t][1], scale2, fmaf(mA.y, LOG2E, bA.y));
        D[t][2] = fmaf(D[t][2], scale2, fmaf(mB.x, LOG2E, bB.x));
        D[t][3] = fmaf(D[t][3], scale2, fmaf(mB.y, LOG2E, bB.y));
    }
    float mxA = -1e30f, mxB = -1e30f;
#pragma unroll
    for (int t = 0; t < 8; t++) {
        mxA = fmaxf(mxA, fmaxf(D[t][0], D[t][1]));
        mxB = fmaxf(mxB, fmaxf(D[t][2], D[t][3]));
    }
    mxA = fmaxf(mxA, __shfl_xor_sync(0xffffffffu, mxA, 1));
    mxA = fmaxf(mxA, __shfl_xor_sync(0xffffffffu, mxA, 2));
    mxB = fmaxf(mxB, __shfl_xor_sync(0xffffffffu, mxB, 1));
    mxB = fmaxf(mxB, __shfl_xor_sync(0xffffffffu, mxB, 2));

    // progressive: exp, sum, pack P (hi/lo) per k-step pair; D dies as ph/pl born
    unsigned ph[4][4], pl[4][4];
    float smA = 0.f, smB = 0.f;
#pragma unroll
    for (int ks = 0; ks < 4; ks++) {
        float e00 = ex2f(D[2 * ks][0] - mxA);
        float e01 = ex2f(D[2 * ks][1] - mxA);
        float e02 = ex2f(D[2 * ks][2] - mxB);
        float e03 = ex2f(D[2 * ks][3] - mxB);
        float e10 = ex2f(D[2 * ks + 1][0] - mxA);
        float e11 = ex2f(D[2 * ks + 1][1] - mxA);
        float e12 = ex2f(D[2 * ks + 1][2] - mxB);
        float e13 = ex2f(D[2 * ks + 1][3] - mxB);
        smA += e00 + e01 + e10 + e11;
        smB += e02 + e03 + e12 + e13;
        ph[ks][0] = pack2(e00, e01);
        ph[ks][1] = pack2(e02, e03);
        ph[ks][2] = pack2(e10, e11);
        ph[ks][3] = pack2(e12, e13);
        pl[ks][0] = pack2(e00 - bflo(ph[ks][0]), e01 - bfhi(ph[ks][0]));
        pl[ks][1] = pack2(e02 - bflo(ph[ks][1]), e03 - bfhi(ph[ks][1]));
        pl[ks][2] = pack2(e10 - bflo(ph[ks][2]), e11 - bfhi(ph[ks][2]));
        pl[ks][3] = pack2(e12 - bflo(ph[ks][3]), e13 - bfhi(ph[ks][3]));
    }
    smA += __shfl_xor_sync(0xffffffffu, smA, 1);
    smA += __shfl_xor_sync(0xffffffffu, smA, 2);
    smB += __shfl_xor_sync(0xffffffffu, smB, 1);
    smB += __shfl_xor_sync(0xffffffffu, smB, 2);
    const float rinvA = 1.f / smA, rinvB = 1.f / smB;
    // P left unnormalized; 1/sum folded into the O store.

    // ---- PV: O[16 x 32] per warp; B = V from [d][m] smem ----
    float O[4][4];
#pragma unroll
    for (int t = 0; t < 4; t++)
#pragma unroll
        for (int c = 0; c < 4; c++) O[t][c] = 0.f;

#pragma unroll
    for (int dt = 0; dt < 4; dt++) {
#pragma unroll
        for (int ks = 0; ks < 4; ks++) {
            const unsigned* vp = svw + (dt * 8 + r) * STV + 8 * ks + cq;
            unsigned bh0 = vp[0], bh1 = vp[4];
            unsigned bl0 = vp[32], bl1 = vp[36];
            MMA(O[dt], ph[ks], bh0, bh1);
            MMA(O[dt], ph[ks], bl0, bl1);
            MMA(O[dt], pl[ks], bh0, bh1);
        }
    }

    // ---- store O (normalize by 1/sum here) ----
    const int yA = (y0 + 2 * wrp) & 255;
    const int yB = (y0 + 2 * wrp + 1) & 255;
    const int xj = (x0 + r) & 255;
#pragma unroll
    for (int dt = 0; dt < 4; dt++) {
        const int d = dt * 8 + 2 * cq;
        out[(chbase + d) * HW + yA * 256 + xj]     = O[dt][0] * rinvA;
        out[(chbase + d + 1) * HW + yA * 256 + xj] = O[dt][1] * rinvA;
        out[(chbase + d) * HW + yB * 256 + xj]     = O[dt][2] * rinvB;
        out[(chbase + d + 1) * HW + yB * 256 + xj] = O[dt][3] * rinvB;
    }
}

// ---------------------------------------------------------------------------
extern "C" void kernel_launch(void* const* d_in, const int* in_sizes, int n_in,
                              void* d_out, int out_size) {
    const float* qkv         = (const float*)d_in[0];
    const float* table       = (const float*)d_in[1];
    const int*   index       = (const int*)  d_in[2];
    const float* mask        = (const float*)d_in[3];
    const float* logit_scale = (const float*)d_in[4];
    const float* w1          = (const float*)d_in[5];
    const float* b1          = (const float*)d_in[6];
    const float* w2          = (const float*)d_in[7];
    float* out = (float*)d_out;

    cudaFuncSetAttribute(win_attn_kernel,
                         cudaFuncAttributePreferredSharedMemoryCarveout, 100);

    bias_mlp_kernel<<<TBL, 128>>>(table, logit_scale, w1, b1, w2);
    bias_gather_kernel<<<96, 256>>>(index);

    float* d_bias = nullptr;
    cudaGetSymbolAddress((void**)&d_bias, g_bias);
    win_attn_kernel<<<2 * 1024 * NH, 128>>>(qkv, mask, d_bias, out);
    (void)in_sizes; (void)n_in; (void)out_size;
}

// round 12
// speedup vs baseline: 1.3273x; 1.0420x over previous
#include <cuda_runtime.h>
#include <cuda_bf16.h>

#define NH 6
#define HD 32
#define NTOK 64
#define HIDDEN 512
#define TBL 225
#define HW 65536

// Per-window Q/K buffer: row n at n*36 + ((n>>2)&15) words; 64 rows + pad.
#define STQK 36
#define SWQK(n) ((n) * STQK + (((n) >> 2) & 15))
#define QKW 2320          // words per Q or K window buffer (64*36+16)
// V: [32][68] words; words 0..31 = m-pair hi, 32..63 = lo.
#define VW 2176           // 32*68
// combined (bias+mask)*log2e fp32: [64][68]
#define CW 4352           // 64*68
#define LOG2E 1.4426950408889634f

// dynamic smem word offsets
#define OFF_SQ 0
#define OFF_SK (4 * QKW)                 // 9280
#define OFF_SV (8 * QKW)                 // 18560
#define OFF_SC (8 * QKW + 4 * VW)        // 27264
#define SMEM_WORDS (OFF_SC + 4 * CW)     // 44672 words = 178688 B

// m16n8k16 row.col f32.bf16.bf16.f32
#define MMA(D, A, b0, b1) \
    asm("mma.sync.aligned.m16n8k16.row.col.f32.bf16.bf16.f32 " \
        "{%0,%1,%2,%3},{%4,%5,%6,%7},{%8,%9},{%0,%1,%2,%3};" \
        : "+f"(D[0]), "+f"(D[1]), "+f"(D[2]), "+f"(D[3]) \
        : "r"(A[0]), "r"(A[1]), "r"(A[2]), "r"(A[3]), "r"(b0), "r"(b1))

__device__ __forceinline__ unsigned pack2(float lo, float hi) {
    unsigned r;
    asm("cvt.rn.bf16x2.f32 %0, %1, %2;" : "=r"(r) : "f"(hi), "f"(lo));
    return r;  // low half = lo, high half = hi
}
__device__ __forceinline__ float bflo(unsigned w) { return __uint_as_float(w << 16); }
__device__ __forceinline__ float bfhi(unsigned w) { return __uint_as_float(w & 0xffff0000u); }
__device__ __forceinline__ float ex2f(float x) {
    float y;
    asm("ex2.approx.ftz.f32 %0, %1;" : "=f"(y) : "f"(x));
    return y;
}

// device-global scratch (no allocations allowed)
__device__ float g_bt[TBL * NH];
__device__ float g_hscale[NH];       // exp(min(ls,max)) * rsqrt(hd) * log2e
__device__ float g_bias[NH * NTOK * NTOK];  // 16*sigmoid(..) * log2e

// ---------------------------------------------------------------------------
// Kernel 0a: CPB MLP, one block per table row (225 blocks) + head scales.
// ---------------------------------------------------------------------------
__global__ void __launch_bounds__(128) bias_mlp_kernel(
    const float* __restrict__ table,
    const float* __restrict__ logit_scale,
    const float* __restrict__ w1,
    const float* __restrict__ b1,
    const float* __restrict__ w2) {
    const int row = blockIdx.x;
    const int tid = threadIdx.x;

    if (row == 0 && tid < NH) {
        const float LOGIT_MAX = 4.605170185988091368f; // log(100)
        g_hscale[tid] = expf(fminf(logit_scale[tid], LOGIT_MAX)) * rsqrtf((float)HD) * LOG2E;
    }

    const float t0 = table[row * 2 + 0];
    const float t1 = table[row * 2 + 1];
    float acc[NH];
#pragma unroll
    for (int h = 0; h < NH; h++) acc[h] = 0.f;

    for (int j = tid; j < HIDDEN; j += 128) {
        float hv = fmaf(t0, w1[j], fmaf(t1, w1[HIDDEN + j], b1[j]));
        hv = fmaxf(hv, 0.f);
#pragma unroll
        for (int h = 0; h < NH; h++) acc[h] = fmaf(hv, w2[j * NH + h], acc[h]);
    }

#pragma unroll
    for (int h = 0; h < NH; h++) {
#pragma unroll
        for (int o = 16; o > 0; o >>= 1)
            acc[h] += __shfl_xor_sync(0xffffffffu, acc[h], o);
    }
    __shared__ float red[4][NH];
    const int warp = tid >> 5;
    if ((tid & 31) == 0) {
#pragma unroll
        for (int h = 0; h < NH; h++) red[warp][h] = acc[h];
    }
    __syncthreads();
    if (tid == 0) {
#pragma unroll
        for (int h = 0; h < NH; h++)
            g_bt[row * NH + h] = red[0][h] + red[1][h] + red[2][h] + red[3][h];
    }
}

// ---------------------------------------------------------------------------
// Kernel 0b: expand bias -> g_bias[h][n][m] = 16*sigmoid(bt[idx][h]) * log2e
// ---------------------------------------------------------------------------
__global__ void bias_gather_kernel(const int* __restrict__ index) {
    int gid = blockIdx.x * blockDim.x + threadIdx.x;
    if (gid >= NH * NTOK * NTOK) return;
    int h = gid >> 12;
    int nm = gid & 4095;
    int r = index[nm];
    float bv = g_bt[r * NH + h];
    g_bias[gid] = (16.f / (1.f + __expf(-bv))) * LOG2E;
}

// ---------------------------------------------------------------------------
// Main kernel: one CTA per (4-window strip, head). 512 threads (16 warps).
//  Strip-coalesced staging (128B-contiguous gmem rows); bf16x3 mma.sync;
//  combined bias+mask staged to smem; 1 CTA/SM (178.6 KB dynamic smem).
// ---------------------------------------------------------------------------
__global__ void __launch_bounds__(512, 1) win_attn_kernel(
    const float* __restrict__ qkv,
    const float* __restrict__ mask,
    const float* __restrict__ bias,
    float* __restrict__ out)
{
    extern __shared__ __align__(16) unsigned dyn[];
    unsigned* const sq_all = dyn + OFF_SQ;
    unsigned* const sk_all = dyn + OFF_SK;
    unsigned* const sv_all = dyn + OFF_SV;
    float* const sc_all = (float*)(dyn + OFF_SC);

    const int tid = threadIdx.x;
    const int bid = blockIdx.x;
    const int h = bid % NH;
    const int s = bid / NH;             // 0..511 strips
    const int b = s >> 8;               // batch
    const int sl = s & 255;
    const int wy = sl >> 3;             // window row 0..31
    const int sx = sl & 7;              // strip col 0..7 (4 windows each)
    const int y0 = wy * 8 + 4;
    const int x0s = sx * 32 + 4;        // strip x origin (shifted by roll)

    // channel = t*384 + b*192 + h*32 + d   (qkv is (3,B,192,H,W))
    const int chbase = b * 192 + h * 32;

    const float* bias_h = bias + h * 4096;

    // ---- stage Q,K: strip-coalesced; unit = (tensor, k-pair, row, float4col) ----
#pragma unroll
    for (int l = 0; l < 4; l++) {
        int u = tid + l * 512;          // 0..2047
        int t = u >> 10;                // 0 = q, 1 = k
        int rem = u & 1023;
        int kp = rem >> 6;              // 0..15
        int i = (rem >> 3) & 7;         // window row
        int o4 = rem & 7;               // float4 col within strip
        int y = (y0 + i) & 255;
        int x = (x0s + 4 * o4) & 255;   // 4-aligned; no intra-float4 wrap
        const float* basep = qkv + (chbase + t * 384 + 2 * kp) * HW + y * 256 + x;
        float4 v0 = *(const float4*)basep;          // channel 2*kp
        float4 v1 = *(const float4*)(basep + HW);   // channel 2*kp+1
        int wloc = o4 >> 1;
        int j0 = (o4 & 1) << 2;
        int n = i * 8 + j0;
        unsigned* rowbase = ((t == 0) ? sq_all : sk_all) + wloc * QKW;
        float a0[4] = {v0.x, v0.y, v0.z, v0.w};
        float a1[4] = {v1.x, v1.y, v1.z, v1.w};
#pragma unroll
        for (int e = 0; e < 4; e++) {
            unsigned hw_ = pack2(a0[e], a1[e]);
            unsigned lw_ = pack2(a0[e] - bflo(hw_), a1[e] - bfhi(hw_));
            int ro = SWQK(n + e);
            rowbase[ro + kp] = hw_;
            rowbase[ro + 16 + kp] = lw_;
        }
    }
    // ---- stage V: strip-coalesced ----
#pragma unroll
    for (int l = 0; l < 4; l++) {
        int u = tid + l * 512;          // 0..2047
        int d = u >> 6;                 // 0..31
        int i = (u >> 3) & 7;
        int o4 = u & 7;
        int y = (y0 + i) & 255;
        int x = (x0s + 4 * o4) & 255;
        float4 v = *(const float4*)(qkv + (chbase + 768 + d) * HW + y * 256 + x);
        int wloc = o4 >> 1;
        int j0 = (o4 & 1) << 2;
        int n = i * 8 + j0;
        unsigned* svw = sv_all + wloc * VW;
        unsigned h0 = pack2(v.x, v.y);
        unsigned h1 = pack2(v.z, v.w);
        unsigned l0 = pack2(v.x - bflo(h0), v.y - bfhi(h0));
        unsigned l1 = pack2(v.z - bflo(h1), v.w - bfhi(h1));
        *(uint2*)&svw[d * 68 + (n >> 1)] = make_uint2(h0, h1);
        *(uint2*)&svw[d * 68 + 32 + (n >> 1)] = make_uint2(l0, l1);
    }
    // ---- stage combined = bias + mask*log2e (per window) ----
#pragma unroll
    for (int l = 0; l < 8; l++) {
        int u = tid + l * 512;          // 0..4095
        int wloc = u >> 10;
        int r4 = u & 1023;
        int n = r4 >> 4;
        int mq = (r4 & 15) << 2;
        float4 bv = *(const float4*)(bias_h + n * 64 + mq);
        const float* mp = mask + (wy * 32 + sx * 4 + wloc) * 4096 + n * 64 + mq;
        float4 mv = *(const float4*)mp;
        *(float4*)&sc_all[wloc * CW + n * 68 + mq] = make_float4(
            fmaf(mv.x, LOG2E, bv.x), fmaf(mv.y, LOG2E, bv.y),
            fmaf(mv.z, LOG2E, bv.z), fmaf(mv.w, LOG2E, bv.w));
    }
    __syncthreads();

    const int lane = tid & 31;
    const int wid = tid >> 5;           // 0..15
    const int wloc = wid >> 2;          // window slot 0..3
    const int wrp = wid & 3;            // warp within window
    const int r = lane >> 2;            // groupID
    const int cq = lane & 3;            // threadID in group
    const int rowA = wrp * 16 + r;      // token row (half A); half B = +8

    const unsigned* sqw = sq_all + wloc * QKW;
    const unsigned* skw = sk_all + wloc * QKW;
    const unsigned* svw = sv_all + wloc * VW;
    const float* scw = sc_all + wloc * CW;
    const int x0 = x0s + 8 * wloc;      // this window's x origin

    // ---- QK^T: A fragments (Q) hoisted; 8 n-tiles x 2 k-steps x 3 splits ----
    unsigned ah[2][4], al[2][4];
#pragma unroll
    for (int ks = 0; ks < 2; ks++) {
        const unsigned* q0 = sqw + SWQK(rowA) + 8 * ks + cq;
        const unsigned* q1 = sqw + SWQK(rowA + 8) + 8 * ks + cq;
        ah[ks][0] = q0[0];  ah[ks][1] = q1[0];  ah[ks][2] = q0[4];  ah[ks][3] = q1[4];
        al[ks][0] = q0[16]; al[ks][1] = q1[16]; al[ks][2] = q0[20]; al[ks][3] = q1[20];
    }

    float D[8][4];
#pragma unroll
    for (int t = 0; t < 8; t++)
#pragma unroll
        for (int c = 0; c < 4; c++) D[t][c] = 0.f;

#pragma unroll
    for (int nt = 0; nt < 8; nt++) {
#pragma unroll
        for (int ks = 0; ks < 2; ks++) {
            const unsigned* kp = skw + SWQK(nt * 8 + r) + 8 * ks + cq;
            unsigned bh0 = kp[0], bh1 = kp[4];
            unsigned bl0 = kp[16], bl1 = kp[20];
            MMA(D[nt], ah[ks], bh0, bh1);
            MMA(D[nt], ah[ks], bl0, bl1);
            MMA(D[nt], al[ks], bh0, bh1);
        }
    }

    // ---- softmax IN PLACE in D, log2 domain; combined from smem ----
    const float scale2 = g_hscale[h];   // includes log2e
    const float* cA_p = scw + rowA * 68 + 2 * cq;
    const float* cB_p = scw + (rowA + 8) * 68 + 2 * cq;
#pragma unroll
    for (int t = 0; t < 8; t++) {
        float2 cA = *(const float2*)(cA_p + t * 8);
        float2 cB = *(const float2*)(cB_p + t * 8);
        D[t][0] = fmaf(D[t][0], scale2, cA.x);
        D[t][1] = fmaf(D[t][1], scale2, cA.y);
        D[t][2] = fmaf(D[t][2], scale2, cB.x);
        D[t][3] = fmaf(D[t][3], scale2, cB.y);
    }
    float mxA = -1e30f, mxB = -1e30f;
#pragma unroll
    for (int t = 0; t < 8; t++) {
        mxA = fmaxf(mxA, fmaxf(D[t][0], D[t][1]));
        mxB = fmaxf(mxB, fmaxf(D[t][2], D[t][3]));
    }
    mxA = fmaxf(mxA, __shfl_xor_sync(0xffffffffu, mxA, 1));
    mxA = fmaxf(mxA, __shfl_xor_sync(0xffffffffu, mxA, 2));
    mxB = fmaxf(mxB, __shfl_xor_sync(0xffffffffu, mxB, 1));
    mxB = fmaxf(mxB, __shfl_xor_sync(0xffffffffu, mxB, 2));

    // progressive: exp, sum, pack P (hi/lo); D dies as ph/pl born
    unsigned ph[4][4], pl[4][4];
    float smA = 0.f, smB = 0.f;
#pragma unroll
    for (int ks = 0; ks < 4; ks++) {
        float e00 = ex2f(D[2 * ks][0] - mxA);
        float e01 = ex2f(D[2 * ks][1] - mxA);
        float e02 = ex2f(D[2 * ks][2] - mxB);
        float e03 = ex2f(D[2 * ks][3] - mxB);
        float e10 = ex2f(D[2 * ks + 1][0] - mxA);
        float e11 = ex2f(D[2 * ks + 1][1] - mxA);
        float e12 = ex2f(D[2 * ks + 1][2] - mxB);
        float e13 = ex2f(D[2 * ks + 1][3] - mxB);
        smA += e00 + e01 + e10 + e11;
        smB += e02 + e03 + e12 + e13;
        ph[ks][0] = pack2(e00, e01);
        ph[ks][1] = pack2(e02, e03);
        ph[ks][2] = pack2(e10, e11);
        ph[ks][3] = pack2(e12, e13);
        pl[ks][0] = pack2(e00 - bflo(ph[ks][0]), e01 - bfhi(ph[ks][0]));
        pl[ks][1] = pack2(e02 - bflo(ph[ks][1]), e03 - bfhi(ph[ks][1]));
        pl[ks][2] = pack2(e10 - bflo(ph[ks][2]), e11 - bfhi(ph[ks][2]));
        pl[ks][3] = pack2(e12 - bflo(ph[ks][3]), e13 - bfhi(ph[ks][3]));
    }
    smA += __shfl_xor_sync(0xffffffffu, smA, 1);
    smA += __shfl_xor_sync(0xffffffffu, smA, 2);
    smB += __shfl_xor_sync(0xffffffffu, smB, 1);
    smB += __shfl_xor_sync(0xffffffffu, smB, 2);
    const float rinvA = 1.f / smA, rinvB = 1.f / smB;
    // P left unnormalized; 1/sum folded into the O store.

    // ---- PV: O[16 x 32] per warp; B = V from [d][m] smem ----
    float O[4][4];
#pragma unroll
    for (int t = 0; t < 4; t++)
#pragma unroll
        for (int c = 0; c < 4; c++) O[t][c] = 0.f;

#pragma unroll
    for (int dt = 0; dt < 4; dt++) {
#pragma unroll
        for (int ks = 0; ks < 4; ks++) {
            const unsigned* vp = svw + (dt * 8 + r) * 68 + 8 * ks + cq;
            unsigned bh0 = vp[0], bh1 = vp[4];
            unsigned bl0 = vp[32], bl1 = vp[36];
            MMA(O[dt], ph[ks], bh0, bh1);
            MMA(O[dt], ph[ks], bl0, bl1);
            MMA(O[dt], pl[ks], bh0, bh1);
        }
    }

    // ---- store O (normalize by 1/sum here) ----
    const int yA = (y0 + 2 * wrp) & 255;
    const int yB = (y0 + 2 * wrp + 1) & 255;
    const int xj = (x0 + r) & 255;
#pragma unroll
    for (int dt = 0; dt < 4; dt++) {
        const int d = dt * 8 + 2 * cq;
        out[(chbase + d) * HW + yA * 256 + xj]     = O[dt][0] * rinvA;
        out[(chbase + d + 1) * HW + yA * 256 + xj] = O[dt][1] * rinvA;
        out[(chbase + d) * HW + yB * 256 + xj]     = O[dt][2] * rinvB;
        out[(chbase + d + 1) * HW + yB * 256 + xj] = O[dt][3] * rinvB;
    }
}

// ---------------------------------------------------------------------------
extern "C" void kernel_launch(void* const* d_in, const int* in_sizes, int n_in,
                              void* d_out, int out_size) {
    const float* qkv         = (const float*)d_in[0];
    const float* table       = (const float*)d_in[1];
    const int*   index       = (const int*)  d_in[2];
    const float* mask        = (const float*)d_in[3];
    const float* logit_scale = (const float*)d_in[4];
    const float* w1          = (const float*)d_in[5];
    const float* b1          = (const float*)d_in[6];
    const float* w2          = (const float*)d_in[7];
    float* out = (float*)d_out;

    const int smem_bytes = SMEM_WORDS * 4;   // 178688
    cudaFuncSetAttribute(win_attn_kernel,
                         cudaFuncAttributeMaxDynamicSharedMemorySize, smem_bytes);
    cudaFuncSetAttribute(win_attn_kernel,
                         cudaFuncAttributePreferredSharedMemoryCarveout, 100);

    bias_mlp_kernel<<<TBL, 128>>>(table, logit_scale, w1, b1, w2);
    bias_gather_kernel<<<96, 256>>>(index);

    float* d_bias = nullptr;
    cudaGetSymbolAddress((void**)&d_bias, g_bias);
    win_attn_kernel<<<512 * NH, 512, smem_bytes>>>(qkv, mask, d_bias, out);
    (void)in_sizes; (void)n_in; (void)out_size;
}

// round 13
// speedup vs baseline: 1.5790x; 1.1896x over previous
#include <cuda_runtime.h>
#include <cuda_bf16.h>

#define NH 6
#define HD 32
#define NTOK 64
#define HIDDEN 512
#define TBL 225
#define HW 65536

// Per-window Q/K buffer: row n at n*36 + ((n>>2)&15) words; 64 rows + pad.
#define STQK 36
#define SWQK(n) ((n) * STQK + (((n) >> 2) & 15))
#define QKW 2320          // words per Q or K window buffer (64*36+16)
// V: [32][68] words; words 0..31 = m-pair hi, 32..63 = lo.
#define VW 2176           // 32*68
// combined (bias+mask)*log2e fp32: [64][68]
#define CW 4352           // 64*68
#define LOG2E 1.4426950408889634f

// dynamic smem word offsets (2 windows per CTA)
#define OFF_SQ 0
#define OFF_SK (2 * QKW)                 // 4640
#define OFF_SV (4 * QKW)                 // 9280
#define OFF_SC (4 * QKW + 2 * VW)        // 13632
#define SMEM_WORDS (OFF_SC + 2 * CW)     // 22336 words = 89344 B

// m16n8k16 row.col f32.bf16.bf16.f32
#define MMA(D, A, b0, b1) \
    asm("mma.sync.aligned.m16n8k16.row.col.f32.bf16.bf16.f32 " \
        "{%0,%1,%2,%3},{%4,%5,%6,%7},{%8,%9},{%0,%1,%2,%3};" \
        : "+f"(D[0]), "+f"(D[1]), "+f"(D[2]), "+f"(D[3]) \
        : "r"(A[0]), "r"(A[1]), "r"(A[2]), "r"(A[3]), "r"(b0), "r"(b1))

__device__ __forceinline__ unsigned pack2(float lo, float hi) {
    unsigned r;
    asm("cvt.rn.bf16x2.f32 %0, %1, %2;" : "=r"(r) : "f"(hi), "f"(lo));
    return r;  // low half = lo, high half = hi
}
__device__ __forceinline__ float bflo(unsigned w) { return __uint_as_float(w << 16); }
__device__ __forceinline__ float bfhi(unsigned w) { return __uint_as_float(w & 0xffff0000u); }
__device__ __forceinline__ float ex2f(float x) {
    float y;
    asm("ex2.approx.ftz.f32 %0, %1;" : "=f"(y) : "f"(x));
    return y;
}

// device-global scratch (no allocations allowed)
__device__ float g_bt[TBL * NH];
__device__ float g_hscale[NH];       // exp(min(ls,max)) * rsqrt(hd) * log2e
__device__ float g_bias[NH * NTOK * NTOK];  // 16*sigmoid(..) * log2e

// ---------------------------------------------------------------------------
// Kernel 0a: CPB MLP, one block per table row (225 blocks) + head scales.
// ---------------------------------------------------------------------------
__global__ void __launch_bounds__(128) bias_mlp_kernel(
    const float* __restrict__ table,
    const float* __restrict__ logit_scale,
    const float* __restrict__ w1,
    const float* __restrict__ b1,
    const float* __restrict__ w2) {
    const int row = blockIdx.x;
    const int tid = threadIdx.x;

    if (row == 0 && tid < NH) {
        const float LOGIT_MAX = 4.605170185988091368f; // log(100)
        g_hscale[tid] = expf(fminf(logit_scale[tid], LOGIT_MAX)) * rsqrtf((float)HD) * LOG2E;
    }

    const float t0 = table[row * 2 + 0];
    const float t1 = table[row * 2 + 1];
    float acc[NH];
#pragma unroll
    for (int h = 0; h < NH; h++) acc[h] = 0.f;

    for (int j = tid; j < HIDDEN; j += 128) {
        float hv = fmaf(t0, w1[j], fmaf(t1, w1[HIDDEN + j], b1[j]));
        hv = fmaxf(hv, 0.f);
#pragma unroll
        for (int h = 0; h < NH; h++) acc[h] = fmaf(hv, w2[j * NH + h], acc[h]);
    }

#pragma unroll
    for (int h = 0; h < NH; h++) {
#pragma unroll
        for (int o = 16; o > 0; o >>= 1)
            acc[h] += __shfl_xor_sync(0xffffffffu, acc[h], o);
    }
    __shared__ float red[4][NH];
    const int warp = tid >> 5;
    if ((tid & 31) == 0) {
#pragma unroll
        for (int h = 0; h < NH; h++) red[warp][h] = acc[h];
    }
    __syncthreads();
    if (tid == 0) {
#pragma unroll
        for (int h = 0; h < NH; h++)
            g_bt[row * NH + h] = red[0][h] + red[1][h] + red[2][h] + red[3][h];
    }
}

// ---------------------------------------------------------------------------
// Kernel 0b: expand bias -> g_bias[h][n][m] = 16*sigmoid(bt[idx][h]) * log2e
// ---------------------------------------------------------------------------
__global__ void bias_gather_kernel(const int* __restrict__ index) {
    int gid = blockIdx.x * blockDim.x + threadIdx.x;
    if (gid >= NH * NTOK * NTOK) return;
    int h = gid >> 12;
    int nm = gid & 4095;
    int r = index[nm];
    float bv = g_bt[r * NH + h];
    g_bias[gid] = (16.f / (1.f + __expf(-bv))) * LOG2E;
}

// ---------------------------------------------------------------------------
// Main kernel: one CTA per (2-window strip, head). 256 threads, 2 CTAs/SM.
//  Strip-coalesced staging; bf16x3 mma.sync; combined bias+mask in smem.
// ---------------------------------------------------------------------------
__global__ void __launch_bounds__(256, 2) win_attn_kernel(
    const float* __restrict__ qkv,
    const float* __restrict__ mask,
    const float* __restrict__ bias,
    float* __restrict__ out)
{
    extern __shared__ __align__(16) unsigned dyn[];
    unsigned* const sq_all = dyn + OFF_SQ;
    unsigned* const sk_all = dyn + OFF_SK;
    unsigned* const sv_all = dyn + OFF_SV;
    float* const sc_all = (float*)(dyn + OFF_SC);

    const int tid = threadIdx.x;
    const int bid = blockIdx.x;
    const int h = bid % NH;
    const int s = bid / NH;             // 0..1023 strips
    const int b = s >> 9;               // batch
    const int sl = s & 511;
    const int wy = sl >> 4;             // window row 0..31
    const int sx = sl & 15;             // strip col 0..15 (2 windows each)
    const int y0 = wy * 8 + 4;
    const int x0s = sx * 16 + 4;        // strip x origin (shifted by roll)

    // channel = t*384 + b*192 + h*32 + d   (qkv is (3,B,192,H,W))
    const int chbase = b * 192 + h * 32;

    const float* bias_h = bias + h * 4096;

    // ---- stage Q,K: strip-coalesced; unit = (tensor, k-pair, row, float4col) ----
#pragma unroll
    for (int l = 0; l < 4; l++) {
        int u = tid + l * 256;          // 0..1023
        int t = u >> 9;                 // 0 = q, 1 = k
        int rem = u & 511;
        int kp = rem >> 5;              // 0..15
        int i = (rem >> 2) & 7;         // window row
        int o4 = rem & 3;               // float4 col within strip (2 windows)
        int y = (y0 + i) & 255;
        int x = (x0s + 4 * o4) & 255;   // 4-aligned; no intra-float4 wrap
        const float* basep = qkv + (chbase + t * 384 + 2 * kp) * HW + y * 256 + x;
        float4 v0 = *(const float4*)basep;          // channel 2*kp
        float4 v1 = *(const float4*)(basep + HW);   // channel 2*kp+1
        int wloc = o4 >> 1;
        int j0 = (o4 & 1) << 2;
        int n = i * 8 + j0;
        unsigned* rowbase = ((t == 0) ? sq_all : sk_all) + wloc * QKW;
        float a0[4] = {v0.x, v0.y, v0.z, v0.w};
        float a1[4] = {v1.x, v1.y, v1.z, v1.w};
#pragma unroll
        for (int e = 0; e < 4; e++) {
            unsigned hw_ = pack2(a0[e], a1[e]);
            unsigned lw_ = pack2(a0[e] - bflo(hw_), a1[e] - bfhi(hw_));
            int ro = SWQK(n + e);
            rowbase[ro + kp] = hw_;
            rowbase[ro + 16 + kp] = lw_;
        }
    }
    // ---- stage V: strip-coalesced ----
#pragma unroll
    for (int l = 0; l < 4; l++) {
        int u = tid + l * 256;          // 0..1023
        int d = u >> 5;                 // 0..31
        int i = (u >> 2) & 7;
        int o4 = u & 3;
        int y = (y0 + i) & 255;
        int x = (x0s + 4 * o4) & 255;
        float4 v = *(const float4*)(qkv + (chbase + 768 + d) * HW + y * 256 + x);
        int wloc = o4 >> 1;
        int j0 = (o4 & 1) << 2;
        int n = i * 8 + j0;
        unsigned* svw = sv_all + wloc * VW;
        unsigned h0 = pack2(v.x, v.y);
        unsigned h1 = pack2(v.z, v.w);
        unsigned l0 = pack2(v.x - bflo(h0), v.y - bfhi(h0));
        unsigned l1 = pack2(v.z - bflo(h1), v.w - bfhi(h1));
        *(uint2*)&svw[d * 68 + (n >> 1)] = make_uint2(h0, h1);
        *(uint2*)&svw[d * 68 + 32 + (n >> 1)] = make_uint2(l0, l1);
    }
    // ---- stage combined = bias + mask*log2e (per window) ----
#pragma unroll
    for (int l = 0; l < 8; l++) {
        int u = tid + l * 256;          // 0..2047
        int wloc = u >> 10;
        int r4 = u & 1023;
        int n = r4 >> 4;
        int mq = (r4 & 15) << 2;
        float4 bv = *(const float4*)(bias_h + n * 64 + mq);
        const float* mp = mask + (wy * 32 + sx * 2 + wloc) * 4096 + n * 64 + mq;
        float4 mv = *(const float4*)mp;
        *(float4*)&sc_all[wloc * CW + n * 68 + mq] = make_float4(
            fmaf(mv.x, LOG2E, bv.x), fmaf(mv.y, LOG2E, bv.y),
            fmaf(mv.z, LOG2E, bv.z), fmaf(mv.w, LOG2E, bv.w));
    }
    __syncthreads();

    const int lane = tid & 31;
    const int wid = tid >> 5;           // 0..7
    const int wloc = wid >> 2;          // window slot 0..1
    const int wrp = wid & 3;            // warp within window
    const int r = lane >> 2;            // groupID
    const int cq = lane & 3;            // threadID in group
    const int rowA = wrp * 16 + r;      // token row (half A); half B = +8

    const unsigned* sqw = sq_all + wloc * QKW;
    const unsigned* skw = sk_all + wloc * QKW;
    const unsigned* svw = sv_all + wloc * VW;
    const float* scw = sc_all + wloc * CW;
    const int x0 = x0s + 8 * wloc;      // this window's x origin

    // ---- QK^T: A fragments (Q) hoisted; 8 n-tiles x 2 k-steps x 3 splits ----
    unsigned ah[2][4], al[2][4];
#pragma unroll
    for (int ks = 0; ks < 2; ks++) {
        const unsigned* q0 = sqw + SWQK(rowA) + 8 * ks + cq;
        const unsigned* q1 = sqw + SWQK(rowA + 8) + 8 * ks + cq;
        ah[ks][0] = q0[0];  ah[ks][1] = q1[0];  ah[ks][2] = q0[4];  ah[ks][3] = q1[4];
        al[ks][0] = q0[16]; al[ks][1] = q1[16]; al[ks][2] = q0[20]; al[ks][3] = q1[20];
    }

    float D[8][4];
#pragma unroll
    for (int t = 0; t < 8; t++)
#pragma unroll
        for (int c = 0; c < 4; c++) D[t][c] = 0.f;

#pragma unroll
    for (int nt = 0; nt < 8; nt++) {
#pragma unroll
        for (int ks = 0; ks < 2; ks++) {
            const unsigned* kp = skw + SWQK(nt * 8 + r) + 8 * ks + cq;
            unsigned bh0 = kp[0], bh1 = kp[4];
            unsigned bl0 = kp[16], bl1 = kp[20];
            MMA(D[nt], ah[ks], bh0, bh1);
            MMA(D[nt], ah[ks], bl0, bl1);
            MMA(D[nt], al[ks], bh0, bh1);
        }
    }

    // ---- softmax IN PLACE in D, log2 domain; combined from smem ----
    const float scale2 = g_hscale[h];   // includes log2e
    const float* cA_p = scw + rowA * 68 + 2 * cq;
    const float* cB_p = scw + (rowA + 8) * 68 + 2 * cq;
#pragma unroll
    for (int t = 0; t < 8; t++) {
        float2 cA = *(const float2*)(cA_p + t * 8);
        float2 cB = *(const float2*)(cB_p + t * 8);
        D[t][0] = fmaf(D[t][0], scale2, cA.x);
        D[t][1] = fmaf(D[t][1], scale2, cA.y);
        D[t][2] = fmaf(D[t][2], scale2, cB.x);
        D[t][3] = fmaf(D[t][3], scale2, cB.y);
    }
    float mxA = -1e30f, mxB = -1e30f;
#pragma unroll
    for (int t = 0; t < 8; t++) {
        mxA = fmaxf(mxA, fmaxf(D[t][0], D[t][1]));
        mxB = fmaxf(mxB, fmaxf(D[t][2], D[t][3]));
    }
    mxA = fmaxf(mxA, __shfl_xor_sync(0xffffffffu, mxA, 1));
    mxA = fmaxf(mxA, __shfl_xor_sync(0xffffffffu, mxA, 2));
    mxB = fmaxf(mxB, __shfl_xor_sync(0xffffffffu, mxB, 1));
    mxB = fmaxf(mxB, __shfl_xor_sync(0xffffffffu, mxB, 2));

    // progressive: exp, sum, pack P (hi/lo); D dies as ph/pl born
    unsigned ph[4][4], pl[4][4];
    float smA = 0.f, smB = 0.f;
#pragma unroll
    for (int ks = 0; ks < 4; ks++) {
        float e00 = ex2f(D[2 * ks][0] - mxA);
        float e01 = ex2f(D[2 * ks][1] - mxA);
        float e02 = ex2f(D[2 * ks][2] - mxB);
        float e03 = ex2f(D[2 * ks][3] - mxB);
        float e10 = ex2f(D[2 * ks + 1][0] - mxA);
        float e11 = ex2f(D[2 * ks + 1][1] - mxA);
        float e12 = ex2f(D[2 * ks + 1][2] - mxB);
        float e13 = ex2f(D[2 * ks + 1][3] - mxB);
        smA += e00 + e01 + e10 + e11;
        smB += e02 + e03 + e12 + e13;
        ph[ks][0] = pack2(e00, e01);
        ph[ks][1] = pack2(e02, e03);
        ph[ks][2] = pack2(e10, e11);
        ph[ks][3] = pack2(e12, e13);
        pl[ks][0] = pack2(e00 - bflo(ph[ks][0]), e01 - bfhi(ph[ks][0]));
        pl[ks][1] = pack2(e02 - bflo(ph[ks][1]), e03 - bfhi(ph[ks][1]));
        pl[ks][2] = pack2(e10 - bflo(ph[ks][2]), e11 - bfhi(ph[ks][2]));
        pl[ks][3] = pack2(e12 - bflo(ph[ks][3]), e13 - bfhi(ph[ks][3]));
    }
    smA += __shfl_xor_sync(0xffffffffu, smA, 1);
    smA += __shfl_xor_sync(0xffffffffu, smA, 2);
    smB += __shfl_xor_sync(0xffffffffu, smB, 1);
    smB += __shfl_xor_sync(0xffffffffu, smB, 2);
    const float rinvA = 1.f / smA, rinvB = 1.f / smB;
    // P left unnormalized; 1/sum folded into the O store.

    // ---- PV: O[16 x 32] per warp; B = V from [d][m] smem ----
    float O[4][4];
#pragma unroll
    for (int t = 0; t < 4; t++)
#pragma unroll
        for (int c = 0; c < 4; c++) O[t][c] = 0.f;

#pragma unroll
    for (int dt = 0; dt < 4; dt++) {
#pragma unroll
        for (int ks = 0; ks < 4; ks++) {
            const unsigned* vp = svw + (dt * 8 + r) * 68 + 8 * ks + cq;
            unsigned bh0 = vp[0], bh1 = vp[4];
            unsigned bl0 = vp[32], bl1 = vp[36];
            MMA(O[dt], ph[ks], bh0, bh1);
            MMA(O[dt], ph[ks], bl0, bl1);
            MMA(O[dt], pl[ks], bh0, bh1);
        }
    }

    // ---- store O (normalize by 1/sum here) ----
    const int yA = (y0 + 2 * wrp) & 255;
    const int yB = (y0 + 2 * wrp + 1) & 255;
    const int xj = (x0 + r) & 255;
#pragma unroll
    for (int dt = 0; dt < 4; dt++) {
        const int d = dt * 8 + 2 * cq;
        out[(chbase + d) * HW + yA * 256 + xj]     = O[dt][0] * rinvA;
        out[(chbase + d + 1) * HW + yA * 256 + xj] = O[dt][1] * rinvA;
        out[(chbase + d) * HW + yB * 256 + xj]     = O[dt][2] * rinvB;
        out[(chbase + d + 1) * HW + yB * 256 + xj] = O[dt][3] * rinvB;
    }
}

// ---------------------------------------------------------------------------
extern "C" void kernel_launch(void* const* d_in, const int* in_sizes, int n_in,
                              void* d_out, int out_size) {
    const float* qkv         = (const float*)d_in[0];
    const float* table       = (const float*)d_in[1];
    const int*   index       = (const int*)  d_in[2];
    const float* mask        = (const float*)d_in[3];
    const float* logit_scale = (const float*)d_in[4];
    const float* w1          = (const float*)d_in[5];
    const float* b1          = (const float*)d_in[6];
    const float* w2          = (const float*)d_in[7];
    float* out = (float*)d_out;

    const int smem_bytes = SMEM_WORDS * 4;   // 89344
    cudaFuncSetAttribute(win_attn_kernel,
                         cudaFuncAttributeMaxDynamicSharedMemorySize, smem_bytes);
    cudaFuncSetAttribute(win_attn_kernel,
                         cudaFuncAttributePreferredSharedMemoryCarveout, 100);

    bias_mlp_kernel<<<TBL, 128>>>(table, logit_scale, w1, b1, w2);
    bias_gather_kernel<<<96, 256>>>(index);

    float* d_bias = nullptr;
    cudaGetSymbolAddress((void**)&d_bias, g_bias);
    win_attn_kernel<<<1024 * NH, 256, smem_bytes>>>(qkv, mask, d_bias, out);
    (void)in_sizes; (void)n_in; (void)out_size;
}

// round 14
// speedup vs baseline: 1.6427x; 1.0404x over previous
#include <cuda_runtime.h>
#include <cuda_bf16.h>

#define NH 6
#define HD 32
#define NTOK 64
#define HIDDEN 512
#define TBL 225
#define HW 65536

// Per-window Q/K buffer: row n at n*36 + ((n>>2)&15) words; 64 rows + pad.
#define STQK 36
#define SWQK(n) ((n) * STQK + (((n) >> 2) & 15))
#define QKW 2320          // words per Q or K window buffer (64*36+16)
// V: [32][68] words; words 0..31 = m-pair hi, 32..63 = lo.
#define VW 2176           // 32*68
// bias (pre-scaled by log2e) fp32: [64][68] -- shared by both windows (head-only)
#define BW 4352           // 64*68
#define LOG2E 1.4426950408889634f

// dynamic smem word offsets (2 windows per CTA)
#define OFF_SQ 0
#define OFF_SK (2 * QKW)                 // 4640
#define OFF_SV (4 * QKW)                 // 9280
#define OFF_SB (4 * QKW + 2 * VW)        // 13632
#define SMEM_WORDS (OFF_SB + BW)         // 17984 words = 71936 B

// m16n8k16 row.col f32.bf16.bf16.f32
#define MMA(D, A, b0, b1) \
    asm("mma.sync.aligned.m16n8k16.row.col.f32.bf16.bf16.f32 " \
        "{%0,%1,%2,%3},{%4,%5,%6,%7},{%8,%9},{%0,%1,%2,%3};" \
        : "+f"(D[0]), "+f"(D[1]), "+f"(D[2]), "+f"(D[3]) \
        : "r"(A[0]), "r"(A[1]), "r"(A[2]), "r"(A[3]), "r"(b0), "r"(b1))

__device__ __forceinline__ unsigned pack2(float lo, float hi) {
    unsigned r;
    asm("cvt.rn.bf16x2.f32 %0, %1, %2;" : "=r"(r) : "f"(hi), "f"(lo));
    return r;  // low half = lo, high half = hi
}
__device__ __forceinline__ float bflo(unsigned w) { return __uint_as_float(w << 16); }
__device__ __forceinline__ float bfhi(unsigned w) { return __uint_as_float(w & 0xffff0000u); }
__device__ __forceinline__ float ex2f(float x) {
    float y;
    asm("ex2.approx.ftz.f32 %0, %1;" : "=f"(y) : "f"(x));
    return y;
}

// device-global scratch (no allocations allowed)
__device__ float g_bt[TBL * NH];
__device__ float g_hscale[NH];       // exp(min(ls,max)) * rsqrt(hd) * log2e
__device__ float g_bias[NH * NTOK * NTOK];  // 16*sigmoid(..) * log2e

// ---------------------------------------------------------------------------
// Kernel 0a: CPB MLP, one block per table row (225 blocks) + head scales.
// ---------------------------------------------------------------------------
__global__ void __launch_bounds__(128) bias_mlp_kernel(
    const float* __restrict__ table,
    const float* __restrict__ logit_scale,
    const float* __restrict__ w1,
    const float* __restrict__ b1,
    const float* __restrict__ w2) {
    const int row = blockIdx.x;
    const int tid = threadIdx.x;

    if (row == 0 && tid < NH) {
        const float LOGIT_MAX = 4.605170185988091368f; // log(100)
        g_hscale[tid] = expf(fminf(logit_scale[tid], LOGIT_MAX)) * rsqrtf((float)HD) * LOG2E;
    }

    const float t0 = table[row * 2 + 0];
    const float t1 = table[row * 2 + 1];
    float acc[NH];
#pragma unroll
    for (int h = 0; h < NH; h++) acc[h] = 0.f;

    for (int j = tid; j < HIDDEN; j += 128) {
        float hv = fmaf(t0, w1[j], fmaf(t1, w1[HIDDEN + j], b1[j]));
        hv = fmaxf(hv, 0.f);
#pragma unroll
        for (int h = 0; h < NH; h++) acc[h] = fmaf(hv, w2[j * NH + h], acc[h]);
    }

#pragma unroll
    for (int h = 0; h < NH; h++) {
#pragma unroll
        for (int o = 16; o > 0; o >>= 1)
            acc[h] += __shfl_xor_sync(0xffffffffu, acc[h], o);
    }
    __shared__ float red[4][NH];
    const int warp = tid >> 5;
    if ((tid & 31) == 0) {
#pragma unroll
        for (int h = 0; h < NH; h++) red[warp][h] = acc[h];
    }
    __syncthreads();
    if (tid == 0) {
#pragma unroll
        for (int h = 0; h < NH; h++)
            g_bt[row * NH + h] = red[0][h] + red[1][h] + red[2][h] + red[3][h];
    }
}

// ---------------------------------------------------------------------------
// Kernel 0b: expand bias -> g_bias[h][n][m] = 16*sigmoid(bt[idx][h]) * log2e
// ---------------------------------------------------------------------------
__global__ void bias_gather_kernel(const int* __restrict__ index) {
    int gid = blockIdx.x * blockDim.x + threadIdx.x;
    if (gid >= NH * NTOK * NTOK) return;
    int h = gid >> 12;
    int nm = gid & 4095;
    int r = index[nm];
    float bv = g_bt[r * NH + h];
    g_bias[gid] = (16.f / (1.f + __expf(-bv))) * LOG2E;
}

// ---------------------------------------------------------------------------
// Main kernel: one CTA per (2-window strip, head). 256 threads, 3 CTAs/SM.
//  Strip-coalesced staging; bf16x3 mma.sync; bias in smem (shared), mask
//  read directly from L2 in the epilogue.
// ---------------------------------------------------------------------------
__global__ void __launch_bounds__(256, 3) win_attn_kernel(
    const float* __restrict__ qkv,
    const float* __restrict__ mask,
    const float* __restrict__ bias,
    float* __restrict__ out)
{
    extern __shared__ __align__(16) unsigned dyn[];
    unsigned* const sq_all = dyn + OFF_SQ;
    unsigned* const sk_all = dyn + OFF_SK;
    unsigned* const sv_all = dyn + OFF_SV;
    float* const sb = (float*)(dyn + OFF_SB);   // bias, shared by both windows

    const int tid = threadIdx.x;
    const int bid = blockIdx.x;
    const int h = bid % NH;
    const int s = bid / NH;             // 0..1023 strips
    const int b = s >> 9;               // batch
    const int sl = s & 511;
    const int wy = sl >> 4;             // window row 0..31
    const int sx = sl & 15;             // strip col 0..15 (2 windows each)
    const int y0 = wy * 8 + 4;
    const int x0s = sx * 16 + 4;        // strip x origin (shifted by roll)

    // channel = t*384 + b*192 + h*32 + d   (qkv is (3,B,192,H,W))
    const int chbase = b * 192 + h * 32;

    const float* bias_h = bias + h * 4096;

    // ---- stage Q,K: strip-coalesced; unit = (tensor, k-pair, row, float4col) ----
#pragma unroll
    for (int l = 0; l < 4; l++) {
        int u = tid + l * 256;          // 0..1023
        int t = u >> 9;                 // 0 = q, 1 = k
        int rem = u & 511;
        int kp = rem >> 5;              // 0..15
        int i = (rem >> 2) & 7;         // window row
        int o4 = rem & 3;               // float4 col within strip (2 windows)
        int y = (y0 + i) & 255;
        int x = (x0s + 4 * o4) & 255;   // 4-aligned; no intra-float4 wrap
        const float* basep = qkv + (chbase + t * 384 + 2 * kp) * HW + y * 256 + x;
        float4 v0 = *(const float4*)basep;          // channel 2*kp
        float4 v1 = *(const float4*)(basep + HW);   // channel 2*kp+1
        int wloc = o4 >> 1;
        int j0 = (o4 & 1) << 2;
        int n = i * 8 + j0;
        unsigned* rowbase = ((t == 0) ? sq_all : sk_all) + wloc * QKW;
        float a0[4] = {v0.x, v0.y, v0.z, v0.w};
        float a1[4] = {v1.x, v1.y, v1.z, v1.w};
#pragma unroll
        for (int e = 0; e < 4; e++) {
            unsigned hw_ = pack2(a0[e], a1[e]);
            unsigned lw_ = pack2(a0[e] - bflo(hw_), a1[e] - bfhi(hw_));
            int ro = SWQK(n + e);
            rowbase[ro + kp] = hw_;
            rowbase[ro + 16 + kp] = lw_;
        }
    }
    // ---- stage V: strip-coalesced ----
#pragma unroll
    for (int l = 0; l < 4; l++) {
        int u = tid + l * 256;          // 0..1023
        int d = u >> 5;                 // 0..31
        int i = (u >> 2) & 7;
        int o4 = u & 3;
        int y = (y0 + i) & 255;
        int x = (x0s + 4 * o4) & 255;
        float4 v = *(const float4*)(qkv + (chbase + 768 + d) * HW + y * 256 + x);
        int wloc = o4 >> 1;
        int j0 = (o4 & 1) << 2;
        int n = i * 8 + j0;
        unsigned* svw = sv_all + wloc * VW;
        unsigned h0 = pack2(v.x, v.y);
        unsigned h1 = pack2(v.z, v.w);
        unsigned l0 = pack2(v.x - bflo(h0), v.y - bfhi(h0));
        unsigned l1 = pack2(v.z - bflo(h1), v.w - bfhi(h1));
        *(uint2*)&svw[d * 68 + (n >> 1)] = make_uint2(h0, h1);
        *(uint2*)&svw[d * 68 + 32 + (n >> 1)] = make_uint2(l0, l1);
    }
    // ---- stage bias (pre-scaled by log2e), shared by both windows ----
#pragma unroll
    for (int l = 0; l < 4; l++) {
        int u = tid + l * 256;          // 0..1023 float4
        int n = u >> 4;
        int mq = (u & 15) << 2;
        float4 bv = *(const float4*)(bias_h + n * 64 + mq);
        *(float4*)&sb[n * 68 + mq] = bv;
    }
    __syncthreads();

    const int lane = tid & 31;
    const int wid = tid >> 5;           // 0..7
    const int wloc = wid >> 2;          // window slot 0..1
    const int wrp = wid & 3;            // warp within window
    const int r = lane >> 2;            // groupID
    const int cq = lane & 3;            // threadID in group
    const int rowA = wrp * 16 + r;      // token row (half A); half B = +8

    const unsigned* sqw = sq_all + wloc * QKW;
    const unsigned* skw = sk_all + wloc * QKW;
    const unsigned* svw = sv_all + wloc * VW;
    const float* mask_w = mask + (wy * 32 + sx * 2 + wloc) * 4096;
    const int x0 = x0s + 8 * wloc;      // this window's x origin

    // ---- QK^T: A fragments (Q) hoisted; 8 n-tiles x 2 k-steps x 3 splits ----
    unsigned ah[2][4], al[2][4];
#pragma unroll
    for (int ks = 0; ks < 2; ks++) {
        const unsigned* q0 = sqw + SWQK(rowA) + 8 * ks + cq;
        const unsigned* q1 = sqw + SWQK(rowA + 8) + 8 * ks + cq;
        ah[ks][0] = q0[0];  ah[ks][1] = q1[0];  ah[ks][2] = q0[4];  ah[ks][3] = q1[4];
        al[ks][0] = q0[16]; al[ks][1] = q1[16]; al[ks][2] = q0[20]; al[ks][3] = q1[20];
    }

    float D[8][4];
#pragma unroll
    for (int t = 0; t < 8; t++)
#pragma unroll
        for (int c = 0; c < 4; c++) D[t][c] = 0.f;

#pragma unroll
    for (int nt = 0; nt < 8; nt++) {
#pragma unroll
        for (int ks = 0; ks < 2; ks++) {
            const unsigned* kp = skw + SWQK(nt * 8 + r) + 8 * ks + cq;
            unsigned bh0 = kp[0], bh1 = kp[4];
            unsigned bl0 = kp[16], bl1 = kp[20];
            MMA(D[nt], ah[ks], bh0, bh1);
            MMA(D[nt], ah[ks], bl0, bl1);
            MMA(D[nt], al[ks], bh0, bh1);
        }
    }

    // ---- softmax IN PLACE in D, log2 domain; bias from smem, mask from L2 ----
    const float scale2 = g_hscale[h];   // includes log2e
    const float* bA_p = sb + rowA * 68 + 2 * cq;
    const float* bB_p = sb + (rowA + 8) * 68 + 2 * cq;
    const float* mA_p = mask_w + rowA * 64 + 2 * cq;
    const float* mB_p = mask_w + (rowA + 8) * 64 + 2 * cq;
#pragma unroll
    for (int t = 0; t < 8; t++) {
        float2 bA = *(const float2*)(bA_p + t * 8);
        float2 mA = *(const float2*)(mA_p + t * 8);
        float2 bB = *(const float2*)(bB_p + t * 8);
        float2 mB = *(const float2*)(mB_p + t * 8);
        D[t][0] = fmaf(D[t][0], scale2, fmaf(mA.x, LOG2E, bA.x));
        D[t][1] = fmaf(D[t][1], scale2, fmaf(mA.y, LOG2E, bA.y));
        D[t][2] = fmaf(D[t][2], scale2, fmaf(mB.x, LOG2E, bB.x));
        D[t][3] = fmaf(D[t][3], scale2, fmaf(mB.y, LOG2E, bB.y));
    }
    float mxA = -1e30f, mxB = -1e30f;
#pragma unroll
    for (int t = 0; t < 8; t++) {
        mxA = fmaxf(mxA, fmaxf(D[t][0], D[t][1]));
        mxB = fmaxf(mxB, fmaxf(D[t][2], D[t][3]));
    }
    mxA = fmaxf(mxA, __shfl_xor_sync(0xffffffffu, mxA, 1));
    mxA = fmaxf(mxA, __shfl_xor_sync(0xffffffffu, mxA, 2));
    mxB = fmaxf(mxB, __shfl_xor_sync(0xffffffffu, mxB, 1));
    mxB = fmaxf(mxB, __shfl_xor_sync(0xffffffffu, mxB, 2));

    // progressive: exp, sum, pack P (hi/lo); D dies as ph/pl born
    unsigned ph[4][4], pl[4][4];
    float smA = 0.f, smB = 0.f;
#pragma unroll
    for (int ks = 0; ks < 4; ks++) {
        float e00 = ex2f(D[2 * ks][0] - mxA);
        float e01 = ex2f(D[2 * ks][1] - mxA);
        float e02 = ex2f(D[2 * ks][2] - mxB);
        float e03 = ex2f(D[2 * ks][3] - mxB);
        float e10 = ex2f(D[2 * ks + 1][0] - mxA);
        float e11 = ex2f(D[2 * ks + 1][1] - mxA);
        float e12 = ex2f(D[2 * ks + 1][2] - mxB);
        float e13 = ex2f(D[2 * ks + 1][3] - mxB);
        smA += e00 + e01 + e10 + e11;
        smB += e02 + e03 + e12 + e13;
        ph[ks][0] = pack2(e00, e01);
        ph[ks][1] = pack2(e02, e03);
        ph[ks][2] = pack2(e10, e11);
        ph[ks][3] = pack2(e12, e13);
        pl[ks][0] = pack2(e00 - bflo(ph[ks][0]), e01 - bfhi(ph[ks][0]));
        pl[ks][1] = pack2(e02 - bflo(ph[ks][1]), e03 - bfhi(ph[ks][1]));
        pl[ks][2] = pack2(e10 - bflo(ph[ks][2]), e11 - bfhi(ph[ks][2]));
        pl[ks][3] = pack2(e12 - bflo(ph[ks][3]), e13 - bfhi(ph[ks][3]));
    }
    smA += __shfl_xor_sync(0xffffffffu, smA, 1);
    smA += __shfl_xor_sync(0xffffffffu, smA, 2);
    smB += __shfl_xor_sync(0xffffffffu, smB, 1);
    smB += __shfl_xor_sync(0xffffffffu, smB, 2);
    const float rinvA = 1.f / smA, rinvB = 1.f / smB;
    // P left unnormalized; 1/sum folded into the O store.

    // ---- PV: O[16 x 32] per warp; B = V from [d][m] smem ----
    float O[4][4];
#pragma unroll
    for (int t = 0; t < 4; t++)
#pragma unroll
        for (int c = 0; c < 4; c++) O[t][c] = 0.f;

#pragma unroll
    for (int dt = 0; dt < 4; dt++) {
#pragma unroll
        for (int ks = 0; ks < 4; ks++) {
            const unsigned* vp = svw + (dt * 8 + r) * 68 + 8 * ks + cq;
            unsigned bh0 = vp[0], bh1 = vp[4];
            unsigned bl0 = vp[32], bl1 = vp[36];
            MMA(O[dt], ph[ks], bh0, bh1);
            MMA(O[dt], ph[ks], bl0, bl1);
            MMA(O[dt], pl[ks], bh0, bh1);
        }
    }

    // ---- store O (normalize by 1/sum here) ----
    const int yA = (y0 + 2 * wrp) & 255;
    const int yB = (y0 + 2 * wrp + 1) & 255;
    const int xj = (x0 + r) & 255;
#pragma unroll
    for (int dt = 0; dt < 4; dt++) {
        const int d = dt * 8 + 2 * cq;
        out[(chbase + d) * HW + yA * 256 + xj]     = O[dt][0] * rinvA;
        out[(chbase + d + 1) * HW + yA * 256 + xj] = O[dt][1] * rinvA;
        out[(chbase + d) * HW + yB * 256 + xj]     = O[dt][2] * rinvB;
        out[(chbase + d + 1) * HW + yB * 256 + xj] = O[dt][3] * rinvB;
    }
}

// ---------------------------------------------------------------------------
extern "C" void kernel_launch(void* const* d_in, const int* in_sizes, int n_in,
                              void* d_out, int out_size) {
    const float* qkv         = (const float*)d_in[0];
    const float* table       = (const float*)d_in[1];
    const int*   index       = (const int*)  d_in[2];
    const float* mask        = (const float*)d_in[3];
    const float* logit_scale = (const float*)d_in[4];
    const float* w1          = (const float*)d_in[5];
    const float* b1          = (const float*)d_in[6];
    const float* w2          = (const float*)d_in[7];
    float* out = (float*)d_out;

    const int smem_bytes = SMEM_WORDS * 4;   // 71936
    cudaFuncSetAttribute(win_attn_kernel,
                         cudaFuncAttributeMaxDynamicSharedMemorySize, smem_bytes);
    cudaFuncSetAttribute(win_attn_kernel,
                         cudaFuncAttributePreferredSharedMemoryCarveout, 100);

    bias_mlp_kernel<<<TBL, 128>>>(table, logit_scale, w1, b1, w2);
    bias_gather_kernel<<<96, 256>>>(index);

    float* d_bias = nullptr;
    cudaGetSymbolAddress((void**)&d_bias, g_bias);
    win_attn_kernel<<<1024 * NH, 256, smem_bytes>>>(qkv, mask, d_bias, out);
    (void)in_sizes; (void)n_in; (void)out_size;
}